// round 2
// baseline (speedup 1.0000x reference)
#include <cuda_runtime.h>

#define BATCH  4
#define MSEQ   2048
#define DMODEL 1024
#define NHEAD  16
#define DKH    64
#define MTOT   (BATCH*MSEQ)   // 8192

// Scratch buffers (device globals: no allocation allowed)
__device__ float g_Q[(size_t)MTOT * DMODEL];
__device__ float g_K[(size_t)MTOT * DMODEL];
__device__ float g_V[(size_t)MTOT * DMODEL];
__device__ float g_O[(size_t)MTOT * DMODEL];

__device__ __forceinline__ float fast_exp2(float x) {
    float y;
    asm("ex2.approx.f32 %0, %1;" : "=f"(y) : "f"(x));
    return y;
}

// ---------------------------------------------------------------------------
// C[M,N] = A[M,K] * B[N,K]^T + bias[N]      (both operands K-contiguous, NT)
// Block tile 128x128, K-step 16, 256 threads, 8x8 per-thread (2x2 of 4x4).
// ---------------------------------------------------------------------------
__global__ __launch_bounds__(256, 2)
void gemm_nt_bias(const float* __restrict__ A, const float* __restrict__ B,
                  const float* __restrict__ bias, float* __restrict__ C,
                  int M, int N, int K)
{
    __shared__ float As[16][132];   // [k][m], pad to 132 for store conflicts
    __shared__ float Bs[16][132];   // [k][n]

    const int tid = threadIdx.x;
    const int bm  = blockIdx.y * 128;
    const int bn  = blockIdx.x * 128;
    const int ty  = tid >> 4;     // 0..15
    const int tx  = tid & 15;     // 0..15

    float acc[8][8];
#pragma unroll
    for (int i = 0; i < 8; ++i)
#pragma unroll
        for (int j = 0; j < 8; ++j) acc[i][j] = 0.f;

    const int lrow = tid >> 2;        // 0..63
    const int lk4  = (tid & 3) * 4;   // 0,4,8,12

    for (int k0 = 0; k0 < K; k0 += 16) {
#pragma unroll
        for (int it = 0; it < 2; ++it) {
            const int row = lrow + it * 64;
            float4 a = *(const float4*)(A + (size_t)(bm + row) * K + k0 + lk4);
            As[lk4 + 0][row] = a.x; As[lk4 + 1][row] = a.y;
            As[lk4 + 2][row] = a.z; As[lk4 + 3][row] = a.w;
            float4 b = *(const float4*)(B + (size_t)(bn + row) * K + k0 + lk4);
            Bs[lk4 + 0][row] = b.x; Bs[lk4 + 1][row] = b.y;
            Bs[lk4 + 2][row] = b.z; Bs[lk4 + 3][row] = b.w;
        }
        __syncthreads();
#pragma unroll
        for (int kk = 0; kk < 16; ++kk) {
            float4 a0 = *(const float4*)&As[kk][ty * 4];
            float4 a1 = *(const float4*)&As[kk][64 + ty * 4];
            float4 b0 = *(const float4*)&Bs[kk][tx * 4];
            float4 b1 = *(const float4*)&Bs[kk][64 + tx * 4];
            float ar[8] = {a0.x, a0.y, a0.z, a0.w, a1.x, a1.y, a1.z, a1.w};
            float br[8] = {b0.x, b0.y, b0.z, b0.w, b1.x, b1.y, b1.z, b1.w};
#pragma unroll
            for (int i = 0; i < 8; ++i)
#pragma unroll
                for (int j = 0; j < 8; ++j)
                    acc[i][j] = fmaf(ar[i], br[j], acc[i][j]);
        }
        __syncthreads();
    }

#pragma unroll
    for (int i = 0; i < 8; ++i) {
        const int r = bm + ((i < 4) ? (ty * 4 + i) : (64 + ty * 4 + i - 4));
#pragma unroll
        for (int jj = 0; jj < 2; ++jj) {
            const int c = bn + jj * 64 + tx * 4;
            float4 o;
            o.x = acc[i][jj * 4 + 0] + bias[c + 0];
            o.y = acc[i][jj * 4 + 1] + bias[c + 1];
            o.z = acc[i][jj * 4 + 2] + bias[c + 2];
            o.w = acc[i][jj * 4 + 3] + bias[c + 3];
            *(float4*)(C + (size_t)r * N + c) = o;
        }
    }
}

// ---------------------------------------------------------------------------
// Flash attention: one block per (b, h, 64-query tile). 256 threads.
// Online softmax in the 2^x domain (scale * log2e folded into Q load).
// ---------------------------------------------------------------------------
#define FA_VPAD 68                 // padded row stride for Vs / Ps
#define FA_SMEM_WORDS (4096 /*QsT*/ + 4096 /*KsT*/ + 64*FA_VPAD /*Vs*/ + \
                       64*FA_VPAD /*Ps*/ + 1024 /*red*/ + 64*3 /*m,l,a*/ + 64 /*msk*/)
#define FA_SMEM_BYTES (FA_SMEM_WORDS * 4)

__global__ __launch_bounds__(256)
void flash_attn(const float* __restrict__ Q, const float* __restrict__ K,
                const float* __restrict__ V, const int* __restrict__ mask,
                float* __restrict__ O)
{
    extern __shared__ float sm[];
    float* QsT = sm;                         // [k][q]   64x64
    float* KsT = QsT + 4096;                 // [k][kv]  64x64
    float* Vs  = KsT + 4096;                 // [kv][d]  64x68
    float* Ps  = Vs + 64 * FA_VPAD;          // [q][kv]  64x68
    float* red = Ps + 64 * FA_VPAD;          // [q][16]
    float* m_s = red + 1024;
    float* l_s = m_s + 64;
    float* a_s = l_s + 64;
    int*   msk = (int*)(a_s + 64);

    const int tid = threadIdx.x;
    const int ty = tid >> 4, tx = tid & 15;
    const int b = blockIdx.z, h = blockIdx.y, qt = blockIdx.x;

    const float* Qp = Q + ((size_t)b * MSEQ + qt * 64) * DMODEL + h * DKH;
    const float* Kp = K + (size_t)b * MSEQ * DMODEL + h * DKH;
    const float* Vp = V + (size_t)b * MSEQ * DMODEL + h * DKH;
    const int*   mp = mask + b * MSEQ;

    const float qscale = 1.4426950408889634f * 0.125f;  // log2(e)/sqrt(64)

    // Load Q tile transposed (with scale folded in)
    {
        const int row = tid >> 2;
        const int c0  = (tid & 3) * 16;
#pragma unroll
        for (int u = 0; u < 4; ++u) {
            float4 q4 = *(const float4*)(Qp + (size_t)row * DMODEL + c0 + u * 4);
            QsT[(c0 + u * 4 + 0) * 64 + row] = q4.x * qscale;
            QsT[(c0 + u * 4 + 1) * 64 + row] = q4.y * qscale;
            QsT[(c0 + u * 4 + 2) * 64 + row] = q4.z * qscale;
            QsT[(c0 + u * 4 + 3) * 64 + row] = q4.w * qscale;
        }
    }
    if (tid < 64) { m_s[tid] = -3.0e38f; l_s[tid] = 0.f; }

    float o[4][4];
#pragma unroll
    for (int i = 0; i < 4; ++i)
#pragma unroll
        for (int j = 0; j < 4; ++j) o[i][j] = 0.f;

    __syncthreads();

    for (int kt = 0; kt < MSEQ / 64; ++kt) {
        // Load K (transposed), V (row-major), mask tile
        {
            const int row = tid >> 2;
            const int c0  = (tid & 3) * 16;
            const float* kp = Kp + (size_t)(kt * 64 + row) * DMODEL;
            const float* vp = Vp + (size_t)(kt * 64 + row) * DMODEL;
#pragma unroll
            for (int u = 0; u < 4; ++u) {
                float4 k4 = *(const float4*)(kp + c0 + u * 4);
                KsT[(c0 + u * 4 + 0) * 64 + row] = k4.x;
                KsT[(c0 + u * 4 + 1) * 64 + row] = k4.y;
                KsT[(c0 + u * 4 + 2) * 64 + row] = k4.z;
                KsT[(c0 + u * 4 + 3) * 64 + row] = k4.w;
                float4 v4 = *(const float4*)(vp + c0 + u * 4);
                *(float4*)&Vs[row * FA_VPAD + c0 + u * 4] = v4;
            }
            if (tid < 64) msk[tid] = mp[kt * 64 + tid];
        }
        __syncthreads();

        // S tile = Q K^T  (4x4 per thread)
        float s[4][4];
#pragma unroll
        for (int i = 0; i < 4; ++i)
#pragma unroll
            for (int j = 0; j < 4; ++j) s[i][j] = 0.f;

#pragma unroll 16
        for (int k = 0; k < 64; ++k) {
            float4 qa = *(const float4*)&QsT[k * 64 + ty * 4];
            float4 kb = *(const float4*)&KsT[k * 64 + tx * 4];
            float qr[4] = {qa.x, qa.y, qa.z, qa.w};
            float kr[4] = {kb.x, kb.y, kb.z, kb.w};
#pragma unroll
            for (int i = 0; i < 4; ++i)
#pragma unroll
                for (int j = 0; j < 4; ++j)
                    s[i][j] = fmaf(qr[i], kr[j], s[i][j]);
        }

        // mask (mask==0 -> -inf-ish in log2 domain)
#pragma unroll
        for (int j = 0; j < 4; ++j) {
            if (msk[tx * 4 + j] == 0) {
#pragma unroll
                for (int i = 0; i < 4; ++i) s[i][j] = -1.0e30f;
            }
        }

        // Row-max partials
#pragma unroll
        for (int i = 0; i < 4; ++i) {
            float mx = fmaxf(fmaxf(s[i][0], s[i][1]), fmaxf(s[i][2], s[i][3]));
            red[(ty * 4 + i) * 16 + tx] = mx;
        }
        __syncthreads();
        if (tid < 64) {
            float mx = red[tid * 16];
#pragma unroll
            for (int q = 1; q < 16; ++q) mx = fmaxf(mx, red[tid * 16 + q]);
            const float mo = m_s[tid];
            const float mn = fmaxf(mo, mx);
            m_s[tid] = mn;
            a_s[tid] = fast_exp2(mo - mn);
        }
        __syncthreads();

        // p = 2^(s-m), write Ps, row-sum partials, rescale o
#pragma unroll
        for (int i = 0; i < 4; ++i) {
            const int r = ty * 4 + i;
            const float mn = m_s[r];
            const float al = a_s[r];
            float p0 = fast_exp2(s[i][0] - mn);
            float p1 = fast_exp2(s[i][1] - mn);
            float p2 = fast_exp2(s[i][2] - mn);
            float p3 = fast_exp2(s[i][3] - mn);
            *(float4*)&Ps[r * FA_VPAD + tx * 4] = make_float4(p0, p1, p2, p3);
            red[r * 16 + tx] = (p0 + p1) + (p2 + p3);
            o[i][0] *= al; o[i][1] *= al; o[i][2] *= al; o[i][3] *= al;
        }
        __syncthreads();
        if (tid < 64) {
            float ssum = 0.f;
#pragma unroll
            for (int q = 0; q < 16; ++q) ssum += red[tid * 16 + q];
            l_s[tid] = l_s[tid] * a_s[tid] + ssum;
        }

        // O += P @ V
#pragma unroll 8
        for (int j = 0; j < 64; ++j) {
            float4 vb = *(const float4*)&Vs[j * FA_VPAD + tx * 4];
            float pr0 = Ps[(ty * 4 + 0) * FA_VPAD + j];
            float pr1 = Ps[(ty * 4 + 1) * FA_VPAD + j];
            float pr2 = Ps[(ty * 4 + 2) * FA_VPAD + j];
            float pr3 = Ps[(ty * 4 + 3) * FA_VPAD + j];
            o[0][0] = fmaf(pr0, vb.x, o[0][0]); o[0][1] = fmaf(pr0, vb.y, o[0][1]);
            o[0][2] = fmaf(pr0, vb.z, o[0][2]); o[0][3] = fmaf(pr0, vb.w, o[0][3]);
            o[1][0] = fmaf(pr1, vb.x, o[1][0]); o[1][1] = fmaf(pr1, vb.y, o[1][1]);
            o[1][2] = fmaf(pr1, vb.z, o[1][2]); o[1][3] = fmaf(pr1, vb.w, o[1][3]);
            o[2][0] = fmaf(pr2, vb.x, o[2][0]); o[2][1] = fmaf(pr2, vb.y, o[2][1]);
            o[2][2] = fmaf(pr2, vb.z, o[2][2]); o[2][3] = fmaf(pr2, vb.w, o[2][3]);
            o[3][0] = fmaf(pr3, vb.x, o[3][0]); o[3][1] = fmaf(pr3, vb.y, o[3][1]);
            o[3][2] = fmaf(pr3, vb.z, o[3][2]); o[3][3] = fmaf(pr3, vb.w, o[3][3]);
        }
        __syncthreads();
    }

    // Epilogue: normalize by l, write to O scratch (B,S,D) layout
    float* Op = O + ((size_t)b * MSEQ + qt * 64) * DMODEL + h * DKH;
#pragma unroll
    for (int i = 0; i < 4; ++i) {
        const int r = ty * 4 + i;
        const float inv = 1.f / l_s[r];
        float4 ov = make_float4(o[i][0] * inv, o[i][1] * inv,
                                o[i][2] * inv, o[i][3] * inv);
        *(float4*)(Op + (size_t)r * DMODEL + tx * 4) = ov;
    }
}

// ---------------------------------------------------------------------------
extern "C" void kernel_launch(void* const* d_in, const int* in_sizes, int n_in,
                              void* d_out, int out_size)
{
    const float* query = (const float*)d_in[0];
    const float* key   = (const float*)d_in[1];
    const float* value = (const float*)d_in[2];
    const int*   mask  = (const int*)  d_in[3];
    const float* Wq = (const float*)d_in[4];
    const float* bq = (const float*)d_in[5];
    const float* Wk = (const float*)d_in[6];
    const float* bk = (const float*)d_in[7];
    const float* Wv = (const float*)d_in[8];
    const float* bv = (const float*)d_in[9];
    const float* Wo = (const float*)d_in[10];
    const float* bo = (const float*)d_in[11];
    float* out = (float*)d_out;

    float *pQ, *pK, *pV, *pO;
    cudaGetSymbolAddress((void**)&pQ, g_Q);
    cudaGetSymbolAddress((void**)&pK, g_K);
    cudaGetSymbolAddress((void**)&pV, g_V);
    cudaGetSymbolAddress((void**)&pO, g_O);

    dim3 gblk(256);
    dim3 ggrid(DMODEL / 128, MTOT / 128);

    gemm_nt_bias<<<ggrid, gblk>>>(query, Wq, bq, pQ, MTOT, DMODEL, DMODEL);
    gemm_nt_bias<<<ggrid, gblk>>>(key,   Wk, bk, pK, MTOT, DMODEL, DMODEL);
    gemm_nt_bias<<<ggrid, gblk>>>(value, Wv, bv, pV, MTOT, DMODEL, DMODEL);

    cudaFuncSetAttribute(flash_attn, cudaFuncAttributeMaxDynamicSharedMemorySize,
                         FA_SMEM_BYTES);
    flash_attn<<<dim3(MSEQ / 64, NHEAD, BATCH), 256, FA_SMEM_BYTES>>>(
        pQ, pK, pV, mask, pO);

    gemm_nt_bias<<<ggrid, gblk>>>(pO, Wo, bo, out, MTOT, DMODEL, DMODEL);
}

// round 4
// speedup vs baseline: 2.7371x; 2.7371x over previous
#include <cuda_runtime.h>
#include <cstdint>

#define BATCH  4
#define MSEQ   2048
#define DMODEL 1024
#define NHEAD  16
#define DKH    64
#define MTOT   (BATCH*MSEQ)   // 8192

// ---------------- scratch (device globals; no allocs allowed) ----------------
__device__ float g_Q[(size_t)MTOT * DMODEL];
__device__ float g_K[(size_t)MTOT * DMODEL];
__device__ float g_V[(size_t)MTOT * DMODEL];
__device__ float g_O[(size_t)MTOT * DMODEL];
__device__ float g_Xq[(size_t)MTOT * DMODEL];
__device__ float g_Xk[(size_t)MTOT * DMODEL];
__device__ float g_Xv[(size_t)MTOT * DMODEL];
__device__ float g_W[(size_t)4 * DMODEL * DMODEL];

// ---------------- helpers ----------------
__device__ __forceinline__ float fast_exp2(float x) {
    float y; asm("ex2.approx.f32 %0, %1;" : "=f"(y) : "f"(x)); return y;
}
__device__ __forceinline__ float tf32_rna(float x) {
    unsigned u; asm("cvt.rna.tf32.f32 %0, %1;" : "=r"(u) : "f"(x));
    return __uint_as_float(u);
}
__device__ __forceinline__ uint32_t smem_u32(const void* p) {
    uint32_t a;
    asm("{ .reg .u64 t; cvta.to.shared.u64 t, %1; cvt.u32.u64 %0, t; }" : "=r"(a) : "l"(p));
    return a;
}
__device__ __forceinline__ void cp_async16(uint32_t dst, const void* src) {
    asm volatile("cp.async.cg.shared.global [%0], [%1], 16;" :: "r"(dst), "l"(src));
}
__device__ __forceinline__ void cp_commit() {
    asm volatile("cp.async.commit_group;" ::: "memory");
}
template <int N> __device__ __forceinline__ void cp_wait() {
    asm volatile("cp.async.wait_group %0;" :: "n"(N) : "memory");
}

// m16n8k8 tf32 MMA (row.col), fp32 accumulate in place
__device__ __forceinline__ void mma_tf32(float c[4],
                                         float a0, float a1, float a2, float a3,
                                         float b0, float b1) {
    uint32_t A0 = __float_as_uint(a0), A1 = __float_as_uint(a1);
    uint32_t A2 = __float_as_uint(a2), A3 = __float_as_uint(a3);
    uint32_t B0 = __float_as_uint(b0), B1 = __float_as_uint(b1);
    asm volatile("mma.sync.aligned.m16n8k8.row.col.f32.tf32.tf32.f32 "
                 "{%0,%1,%2,%3},{%4,%5,%6,%7},{%8,%9},{%0,%1,%2,%3};"
                 : "+f"(c[0]), "+f"(c[1]), "+f"(c[2]), "+f"(c[3])
                 : "r"(A0), "r"(A1), "r"(A2), "r"(A3), "r"(B0), "r"(B1));
}

// ---------------------------------------------------------------------------
// tf32 RNA rounding pass
// ---------------------------------------------------------------------------
__global__ void round_tf32_k(const float4* __restrict__ src, float4* __restrict__ dst, int n4) {
    int i = blockIdx.x * blockDim.x + threadIdx.x;
    if (i < n4) {
        float4 v = src[i];
        v.x = tf32_rna(v.x); v.y = tf32_rna(v.y);
        v.z = tf32_rna(v.z); v.w = tf32_rna(v.w);
        dst[i] = v;
    }
}

// ---------------------------------------------------------------------------
// mma.sync tf32 NT GEMM: C[M,1024] = A[M,1024] * B[1024,1024]^T + bias
// CTA 128x128, 8 warps (4m x 2n), warp 32x64. K-chunk 32, 2-stage cp.async.
// Smem rows padded to 36 floats (144B): fragment loads hit banks 4g+t (no conflict).
// ---------------------------------------------------------------------------
#define GP        36                         // padded floats per 32-K row
#define G_HALF    (128 * GP * 4)             // 18432 B  (one matrix, one stage)
#define G_STAGE   (2 * G_HALF)               // 36864 B  (A+B)
#define G_SMEM    (2 * G_STAGE)              // 73728 B

__device__ __forceinline__ void g_load(uint32_t dstA, uint32_t dstB,
                                       const float* __restrict__ A,
                                       const float* __restrict__ B,
                                       int bm, int bn, int k0, int tid) {
#pragma unroll
    for (int i = 0; i < 4; ++i) {
        const int idx = tid + i * 256;
        const int row = idx >> 3, q = idx & 7;
        cp_async16(dstA + row * (GP * 4) + q * 16,
                   A + (size_t)(bm + row) * DMODEL + k0 + q * 4);
        cp_async16(dstB + row * (GP * 4) + q * 16,
                   B + (size_t)(bn + row) * DMODEL + k0 + q * 4);
    }
}

__global__ __launch_bounds__(256)
void gemm_mma(const float* __restrict__ A, const float* __restrict__ B,
              const float* __restrict__ bias, float* __restrict__ C)
{
    extern __shared__ __align__(16) char smem[];
    const uint32_t sb = smem_u32(smem);
    const int tid  = threadIdx.x;
    const int lane = tid & 31, wid = tid >> 5;
    const int g = lane >> 2, t = lane & 3;
    const int wm = wid & 3, wn = wid >> 2;
    const int bm = blockIdx.y * 128, bn = blockIdx.x * 128;

    float acc[2][8][4];
#pragma unroll
    for (int ms = 0; ms < 2; ++ms)
#pragma unroll
        for (int ns = 0; ns < 8; ++ns)
#pragma unroll
            for (int k = 0; k < 4; ++k) acc[ms][ns][k] = 0.f;

    g_load(sb,           sb + G_HALF,           A, B, bm, bn, 0,  tid);
    cp_commit();
    g_load(sb + G_STAGE, sb + G_STAGE + G_HALF, A, B, bm, bn, 32, tid);
    cp_commit();

    const int NCH = DMODEL / 32;   // 32 chunks
    for (int c = 0; c < NCH; ++c) {
        if (c < NCH - 1) cp_wait<1>(); else cp_wait<0>();
        __syncthreads();

        const int s = c & 1;
        const float* As = (const float*)(smem + s * G_STAGE);
        const float* Bs = (const float*)(smem + s * G_STAGE + G_HALF);
#pragma unroll
        for (int ks = 0; ks < 4; ++ks) {
            float a[2][4];
#pragma unroll
            for (int ms = 0; ms < 2; ++ms) {
                const float* ap = As + (wm * 32 + ms * 16 + g) * GP + ks * 8 + t;
                a[ms][0] = ap[0];
                a[ms][1] = ap[8 * GP];
                a[ms][2] = ap[4];
                a[ms][3] = ap[8 * GP + 4];
            }
#pragma unroll
            for (int ns = 0; ns < 8; ++ns) {
                const float* bp = Bs + (wn * 64 + ns * 8 + g) * GP + ks * 8 + t;
                const float b0 = bp[0], b1 = bp[4];
                mma_tf32(acc[0][ns], a[0][0], a[0][1], a[0][2], a[0][3], b0, b1);
                mma_tf32(acc[1][ns], a[1][0], a[1][1], a[1][2], a[1][3], b0, b1);
            }
        }
        __syncthreads();
        if (c + 2 < NCH) {
            g_load(sb + s * G_STAGE, sb + s * G_STAGE + G_HALF,
                   A, B, bm, bn, (c + 2) * 32, tid);
            cp_commit();
        }
    }

#pragma unroll
    for (int ms = 0; ms < 2; ++ms) {
        const int r0 = bm + wm * 32 + ms * 16 + g;
#pragma unroll
        for (int ns = 0; ns < 8; ++ns) {
            const int col = bn + wn * 64 + ns * 8 + 2 * t;
            const float2 bv = *(const float2*)(bias + col);
            float2 lo, hi;
            lo.x = acc[ms][ns][0] + bv.x; lo.y = acc[ms][ns][1] + bv.y;
            hi.x = acc[ms][ns][2] + bv.x; hi.y = acc[ms][ns][3] + bv.y;
            *(float2*)(C + (size_t)r0 * DMODEL + col) = lo;
            *(float2*)(C + (size_t)(r0 + 8) * DMODEL + col) = hi;
        }
    }
}

// ---------------------------------------------------------------------------
// Flash attention with mma.sync tf32.
// 128 threads (4 warps); block = 128 q rows; warp = 32 q rows x full 64 kv.
// S/P live in MMA C-fragments; softmax stats via 4-lane shfl; P remapped to
// A-fragment layout with shfl.idx (no smem round-trip).
// ---------------------------------------------------------------------------
#define QPAD 68
#define VPAD 72
#define FA_SMEM_BYTES ((128*QPAD + 64*QPAD + 64*VPAD) * 4 + 64 * 4)

__global__ __launch_bounds__(128)
void flash_mma(const float* __restrict__ Q, const float* __restrict__ K,
               const float* __restrict__ V, const int* __restrict__ mask,
               float* __restrict__ O)
{
    extern __shared__ __align__(16) float sm[];
    float* Qs = sm;                       // [128][QPAD]
    float* Ks = Qs + 128 * QPAD;          // [64][QPAD]
    float* Vs = Ks + 64 * QPAD;           // [64][VPAD]
    int*   mk = (int*)(Vs + 64 * VPAD);   // [64]

    const int tid  = threadIdx.x;
    const int lane = tid & 31, w = tid >> 5;
    const int g = lane >> 2, t = lane & 3;
    const int b = blockIdx.z, h = blockIdx.y, qt = blockIdx.x;

    const float qscale = 1.4426950408889634f * 0.125f;   // log2(e)/sqrt(64)
    const float NEG = -1.4426950408889634e9f;            // -1e9 * log2(e)

    // ---- load Q tile (scaled + rna) ----
    {
        const float* qp = Q + ((size_t)b * MSEQ + qt * 128 + tid) * DMODEL + h * DKH;
        float* qs = Qs + tid * QPAD;
#pragma unroll
        for (int j = 0; j < 16; ++j) {
            float4 v = *(const float4*)(qp + j * 4);
            qs[j * 4 + 0] = tf32_rna(v.x * qscale);
            qs[j * 4 + 1] = tf32_rna(v.y * qscale);
            qs[j * 4 + 2] = tf32_rna(v.z * qscale);
            qs[j * 4 + 3] = tf32_rna(v.w * qscale);
        }
    }

    float m_[2][2], l_[2][2];
#pragma unroll
    for (int ms = 0; ms < 2; ++ms) {
        m_[ms][0] = -3.0e38f; m_[ms][1] = -3.0e38f;
        l_[ms][0] = 0.f;      l_[ms][1] = 0.f;
    }
    float o[2][8][4];
#pragma unroll
    for (int ms = 0; ms < 2; ++ms)
#pragma unroll
        for (int ns = 0; ns < 8; ++ns)
#pragma unroll
            for (int k = 0; k < 4; ++k) o[ms][ns][k] = 0.f;

    const float* Kbase = K + (size_t)b * MSEQ * DMODEL + h * DKH;
    const float* Vbase = V + (size_t)b * MSEQ * DMODEL + h * DKH;
    const int*   mp    = mask + b * MSEQ;

    __syncthreads();

    for (int kt = 0; kt < MSEQ / 64; ++kt) {
        // ---- load K/V tiles (rna) + mask ----
        {
            const int row = tid & 63, half = tid >> 6;
            const float* kp = Kbase + (size_t)(kt * 64 + row) * DMODEL + half * 32;
            const float* vp = Vbase + (size_t)(kt * 64 + row) * DMODEL + half * 32;
            float* ks = Ks + row * QPAD + half * 32;
            float* vs = Vs + row * VPAD + half * 32;
#pragma unroll
            for (int j = 0; j < 8; ++j) {
                float4 kv = *(const float4*)(kp + j * 4);
                ks[j * 4 + 0] = tf32_rna(kv.x); ks[j * 4 + 1] = tf32_rna(kv.y);
                ks[j * 4 + 2] = tf32_rna(kv.z); ks[j * 4 + 3] = tf32_rna(kv.w);
                float4 vv = *(const float4*)(vp + j * 4);
                vs[j * 4 + 0] = tf32_rna(vv.x); vs[j * 4 + 1] = tf32_rna(vv.y);
                vs[j * 4 + 2] = tf32_rna(vv.z); vs[j * 4 + 3] = tf32_rna(vv.w);
            }
            if (tid < 64) mk[tid] = mp[kt * 64 + tid];
        }
        __syncthreads();

        // ---- S = Q K^T ----
        float s_[2][8][4];
#pragma unroll
        for (int ms = 0; ms < 2; ++ms)
#pragma unroll
            for (int ns = 0; ns < 8; ++ns)
#pragma unroll
                for (int k = 0; k < 4; ++k) s_[ms][ns][k] = 0.f;

#pragma unroll
        for (int ds = 0; ds < 8; ++ds) {
            float a[2][4];
#pragma unroll
            for (int ms = 0; ms < 2; ++ms) {
                const float* ap = Qs + (w * 32 + ms * 16 + g) * QPAD + ds * 8 + t;
                a[ms][0] = ap[0];
                a[ms][1] = ap[8 * QPAD];
                a[ms][2] = ap[4];
                a[ms][3] = ap[8 * QPAD + 4];
            }
#pragma unroll
            for (int ns = 0; ns < 8; ++ns) {
                const float* bp = Ks + (ns * 8 + g) * QPAD + ds * 8 + t;
                const float b0 = bp[0], b1 = bp[4];
                mma_tf32(s_[0][ns], a[0][0], a[0][1], a[0][2], a[0][3], b0, b1);
                mma_tf32(s_[1][ns], a[1][0], a[1][1], a[1][2], a[1][3], b0, b1);
            }
        }

        // ---- mask + online softmax (registers + 4-lane shfl) ----
        int mask0[8], mask1[8];
#pragma unroll
        for (int ns = 0; ns < 8; ++ns) {
            mask0[ns] = mk[ns * 8 + 2 * t];
            mask1[ns] = mk[ns * 8 + 2 * t + 1];
        }
#pragma unroll
        for (int ms = 0; ms < 2; ++ms) {
#pragma unroll
            for (int ns = 0; ns < 8; ++ns) {
                if (!mask0[ns]) { s_[ms][ns][0] = NEG; s_[ms][ns][2] = NEG; }
                if (!mask1[ns]) { s_[ms][ns][1] = NEG; s_[ms][ns][3] = NEG; }
            }
            float mx0 = s_[ms][0][0], mx1 = s_[ms][0][2];
#pragma unroll
            for (int ns = 0; ns < 8; ++ns) {
                mx0 = fmaxf(mx0, fmaxf(s_[ms][ns][0], s_[ms][ns][1]));
                mx1 = fmaxf(mx1, fmaxf(s_[ms][ns][2], s_[ms][ns][3]));
            }
            mx0 = fmaxf(mx0, __shfl_xor_sync(0xffffffffu, mx0, 1));
            mx0 = fmaxf(mx0, __shfl_xor_sync(0xffffffffu, mx0, 2));
            mx1 = fmaxf(mx1, __shfl_xor_sync(0xffffffffu, mx1, 1));
            mx1 = fmaxf(mx1, __shfl_xor_sync(0xffffffffu, mx1, 2));

            const float mn0 = fmaxf(m_[ms][0], mx0);
            const float mn1 = fmaxf(m_[ms][1], mx1);
            const float al0 = fast_exp2(m_[ms][0] - mn0);
            const float al1 = fast_exp2(m_[ms][1] - mn1);
            m_[ms][0] = mn0; m_[ms][1] = mn1;

            float sum0 = 0.f, sum1 = 0.f;
#pragma unroll
            for (int ns = 0; ns < 8; ++ns) {
                float p0 = fast_exp2(s_[ms][ns][0] - mn0);
                float p1 = fast_exp2(s_[ms][ns][1] - mn0);
                float p2 = fast_exp2(s_[ms][ns][2] - mn1);
                float p3 = fast_exp2(s_[ms][ns][3] - mn1);
                sum0 += p0 + p1; sum1 += p2 + p3;
                s_[ms][ns][0] = tf32_rna(p0); s_[ms][ns][1] = tf32_rna(p1);
                s_[ms][ns][2] = tf32_rna(p2); s_[ms][ns][3] = tf32_rna(p3);
            }
            sum0 += __shfl_xor_sync(0xffffffffu, sum0, 1);
            sum0 += __shfl_xor_sync(0xffffffffu, sum0, 2);
            sum1 += __shfl_xor_sync(0xffffffffu, sum1, 1);
            sum1 += __shfl_xor_sync(0xffffffffu, sum1, 2);
            l_[ms][0] = l_[ms][0] * al0 + sum0;
            l_[ms][1] = l_[ms][1] * al1 + sum1;
#pragma unroll
            for (int ns = 0; ns < 8; ++ns) {
                o[ms][ns][0] *= al0; o[ms][ns][1] *= al0;
                o[ms][ns][2] *= al1; o[ms][ns][3] *= al1;
            }
        }

        // ---- O += P V ----
        const int srcA = (lane & ~3) | (t >> 1);
        const int srcB = srcA + 2;
        const bool hi = (t & 1);
#pragma unroll
        for (int s8 = 0; s8 < 8; ++s8) {
            float a[2][4];
#pragma unroll
            for (int ms = 0; ms < 2; ++ms) {
                float v0 = __shfl_sync(0xffffffffu, s_[ms][s8][0], srcA);
                float v1 = __shfl_sync(0xffffffffu, s_[ms][s8][1], srcA);
                a[ms][0] = hi ? v1 : v0;
                float v2 = __shfl_sync(0xffffffffu, s_[ms][s8][2], srcA);
                float v3 = __shfl_sync(0xffffffffu, s_[ms][s8][3], srcA);
                a[ms][1] = hi ? v3 : v2;
                float w0 = __shfl_sync(0xffffffffu, s_[ms][s8][0], srcB);
                float w1 = __shfl_sync(0xffffffffu, s_[ms][s8][1], srcB);
                a[ms][2] = hi ? w1 : w0;
                float w2 = __shfl_sync(0xffffffffu, s_[ms][s8][2], srcB);
                float w3 = __shfl_sync(0xffffffffu, s_[ms][s8][3], srcB);
                a[ms][3] = hi ? w3 : w2;
            }
#pragma unroll
            for (int ns = 0; ns < 8; ++ns) {
                const float* vp = Vs + (s8 * 8 + t) * VPAD + ns * 8 + g;
                const float b0 = vp[0], b1 = vp[4 * VPAD];
                mma_tf32(o[0][ns], a[0][0], a[0][1], a[0][2], a[0][3], b0, b1);
                mma_tf32(o[1][ns], a[1][0], a[1][1], a[1][2], a[1][3], b0, b1);
            }
        }
        __syncthreads();
    }

    // ---- epilogue: normalize, rna, store ----
#pragma unroll
    for (int ms = 0; ms < 2; ++ms) {
        const int r = w * 32 + ms * 16 + g;
        const float inv0 = 1.f / l_[ms][0];
        const float inv1 = 1.f / l_[ms][1];
        float* o0p = O + ((size_t)b * MSEQ + qt * 128 + r) * DMODEL + h * DKH;
        float* o1p = o0p + 8 * DMODEL;
#pragma unroll
        for (int ns = 0; ns < 8; ++ns) {
            const int col = ns * 8 + 2 * t;
            float2 lo, hi2;
            lo.x  = tf32_rna(o[ms][ns][0] * inv0);
            lo.y  = tf32_rna(o[ms][ns][1] * inv0);
            hi2.x = tf32_rna(o[ms][ns][2] * inv1);
            hi2.y = tf32_rna(o[ms][ns][3] * inv1);
            *(float2*)(o0p + col) = lo;
            *(float2*)(o1p + col) = hi2;
        }
    }
}

// ---------------------------------------------------------------------------
extern "C" void kernel_launch(void* const* d_in, const int* in_sizes, int n_in,
                              void* d_out, int out_size)
{
    const float* query = (const float*)d_in[0];
    const float* key   = (const float*)d_in[1];
    const float* value = (const float*)d_in[2];
    const int*   mask  = (const int*)  d_in[3];
    const float* Wq = (const float*)d_in[4];
    const float* bq = (const float*)d_in[5];
    const float* Wk = (const float*)d_in[6];
    const float* bk = (const float*)d_in[7];
    const float* Wv = (const float*)d_in[8];
    const float* bv = (const float*)d_in[9];
    const float* Wo = (const float*)d_in[10];
    const float* bo = (const float*)d_in[11];
    float* out = (float*)d_out;

    float *pQ, *pK, *pV, *pO, *pXq, *pXk, *pXv, *pW;
    cudaGetSymbolAddress((void**)&pQ,  g_Q);
    cudaGetSymbolAddress((void**)&pK,  g_K);
    cudaGetSymbolAddress((void**)&pV,  g_V);
    cudaGetSymbolAddress((void**)&pO,  g_O);
    cudaGetSymbolAddress((void**)&pXq, g_Xq);
    cudaGetSymbolAddress((void**)&pXk, g_Xk);
    cudaGetSymbolAddress((void**)&pXv, g_Xv);
    cudaGetSymbolAddress((void**)&pW,  g_W);

    const int nin4 = MTOT * DMODEL / 4;
    const int nw4  = DMODEL * DMODEL / 4;
    round_tf32_k<<<(nin4 + 255) / 256, 256>>>((const float4*)query, (float4*)pXq, nin4);
    round_tf32_k<<<(nin4 + 255) / 256, 256>>>((const float4*)key,   (float4*)pXk, nin4);
    round_tf32_k<<<(nin4 + 255) / 256, 256>>>((const float4*)value, (float4*)pXv, nin4);
    round_tf32_k<<<(nw4 + 255) / 256, 256>>>((const float4*)Wq, (float4*)(pW + 0 * (size_t)DMODEL * DMODEL), nw4);
    round_tf32_k<<<(nw4 + 255) / 256, 256>>>((const float4*)Wk, (float4*)(pW + 1 * (size_t)DMODEL * DMODEL), nw4);
    round_tf32_k<<<(nw4 + 255) / 256, 256>>>((const float4*)Wv, (float4*)(pW + 2 * (size_t)DMODEL * DMODEL), nw4);
    round_tf32_k<<<(nw4 + 255) / 256, 256>>>((const float4*)Wo, (float4*)(pW + 3 * (size_t)DMODEL * DMODEL), nw4);

    cudaFuncSetAttribute(gemm_mma, cudaFuncAttributeMaxDynamicSharedMemorySize, G_SMEM);
    cudaFuncSetAttribute(flash_mma, cudaFuncAttributeMaxDynamicSharedMemorySize, FA_SMEM_BYTES);

    dim3 ggrid(DMODEL / 128, MTOT / 128);   // (8, 64)
    gemm_mma<<<ggrid, 256, G_SMEM>>>(pXq, pW + 0 * (size_t)DMODEL * DMODEL, bq, pQ);
    gemm_mma<<<ggrid, 256, G_SMEM>>>(pXk, pW + 1 * (size_t)DMODEL * DMODEL, bk, pK);
    gemm_mma<<<ggrid, 256, G_SMEM>>>(pXv, pW + 2 * (size_t)DMODEL * DMODEL, bv, pV);

    flash_mma<<<dim3(MSEQ / 128, NHEAD, BATCH), 128, FA_SMEM_BYTES>>>(pQ, pK, pV, mask, pO);

    gemm_mma<<<ggrid, 256, G_SMEM>>>(pO, pW + 3 * (size_t)DMODEL * DMODEL, bo, out);
}

// round 5
// speedup vs baseline: 3.7725x; 1.3783x over previous
#include <cuda_runtime.h>
#include <cstdint>

#define BATCH  4
#define MSEQ   2048
#define DMODEL 1024
#define NHEAD  16
#define DKH    64
#define MTOT   (BATCH*MSEQ)   // 8192

// ---------------- scratch (device globals; no allocs allowed) ----------------
__device__ float g_Q[(size_t)MTOT * DMODEL];
__device__ float g_K[(size_t)MTOT * DMODEL];
__device__ float g_V[(size_t)MTOT * DMODEL];
__device__ float g_O[(size_t)MTOT * DMODEL];
__device__ float g_Xq[(size_t)MTOT * DMODEL];
__device__ float g_Xk[(size_t)MTOT * DMODEL];
__device__ float g_Xv[(size_t)MTOT * DMODEL];
__device__ float g_W[(size_t)4 * DMODEL * DMODEL];

// ---------------- helpers ----------------
__device__ __forceinline__ float fast_exp2(float x) {
    float y; asm("ex2.approx.f32 %0, %1;" : "=f"(y) : "f"(x)); return y;
}
__device__ __forceinline__ float tf32_rna(float x) {
    unsigned u; asm("cvt.rna.tf32.f32 %0, %1;" : "=r"(u) : "f"(x));
    return __uint_as_float(u);
}
__device__ __forceinline__ uint32_t f16x2_pack(float lo, float hi) {
    uint32_t r; asm("cvt.rn.f16x2.f32 %0, %1, %2;" : "=r"(r) : "f"(hi), "f"(lo));
    return r;
}
__device__ __forceinline__ uint32_t smem_u32(const void* p) {
    uint32_t a;
    asm("{ .reg .u64 t; cvta.to.shared.u64 t, %1; cvt.u32.u64 %0, t; }" : "=r"(a) : "l"(p));
    return a;
}
__device__ __forceinline__ void cp_async16(uint32_t dst, const void* src) {
    asm volatile("cp.async.cg.shared.global [%0], [%1], 16;" :: "r"(dst), "l"(src));
}
__device__ __forceinline__ void cp_commit() {
    asm volatile("cp.async.commit_group;" ::: "memory");
}
template <int N> __device__ __forceinline__ void cp_wait() {
    asm volatile("cp.async.wait_group %0;" :: "n"(N) : "memory");
}

// m16n8k8 tf32 MMA (row.col), fp32 accumulate in place
__device__ __forceinline__ void mma_tf32(float c[4],
                                         float a0, float a1, float a2, float a3,
                                         float b0, float b1) {
    uint32_t A0 = __float_as_uint(a0), A1 = __float_as_uint(a1);
    uint32_t A2 = __float_as_uint(a2), A3 = __float_as_uint(a3);
    uint32_t B0 = __float_as_uint(b0), B1 = __float_as_uint(b1);
    asm volatile("mma.sync.aligned.m16n8k8.row.col.f32.tf32.tf32.f32 "
                 "{%0,%1,%2,%3},{%4,%5,%6,%7},{%8,%9},{%0,%1,%2,%3};"
                 : "+f"(c[0]), "+f"(c[1]), "+f"(c[2]), "+f"(c[3])
                 : "r"(A0), "r"(A1), "r"(A2), "r"(A3), "r"(B0), "r"(B1));
}

// m16n8k16 f16 MMA (row.col), fp32 accumulate in place
__device__ __forceinline__ void mma_f16(float c[4],
                                        uint32_t a0, uint32_t a1, uint32_t a2, uint32_t a3,
                                        uint32_t b0, uint32_t b1) {
    asm volatile("mma.sync.aligned.m16n8k16.row.col.f32.f16.f16.f32 "
                 "{%0,%1,%2,%3},{%4,%5,%6,%7},{%8,%9},{%0,%1,%2,%3};"
                 : "+f"(c[0]), "+f"(c[1]), "+f"(c[2]), "+f"(c[3])
                 : "r"(a0), "r"(a1), "r"(a2), "r"(a3), "r"(b0), "r"(b1));
}

// ---------------------------------------------------------------------------
// tf32 RNA rounding passes (merged launches)
// ---------------------------------------------------------------------------
__global__ void round_inputs_k(const float4* __restrict__ s0, const float4* __restrict__ s1,
                               const float4* __restrict__ s2,
                               float4* __restrict__ d0, float4* __restrict__ d1,
                               float4* __restrict__ d2, int n4) {
    int i = blockIdx.x * blockDim.x + threadIdx.x;
    if (i >= n4) return;
    const float4* s = (blockIdx.y == 0) ? s0 : (blockIdx.y == 1) ? s1 : s2;
    float4*       d = (blockIdx.y == 0) ? d0 : (blockIdx.y == 1) ? d1 : d2;
    float4 v = s[i];
    v.x = tf32_rna(v.x); v.y = tf32_rna(v.y);
    v.z = tf32_rna(v.z); v.w = tf32_rna(v.w);
    d[i] = v;
}
__global__ void round_weights_k(const float4* __restrict__ w0, const float4* __restrict__ w1,
                                const float4* __restrict__ w2, const float4* __restrict__ w3,
                                float4* __restrict__ dst, int n4) {
    int i = blockIdx.x * blockDim.x + threadIdx.x;
    if (i >= n4) return;
    const float4* s = (blockIdx.y == 0) ? w0 : (blockIdx.y == 1) ? w1
                    : (blockIdx.y == 2) ? w2 : w3;
    float4 v = s[i];
    v.x = tf32_rna(v.x); v.y = tf32_rna(v.y);
    v.z = tf32_rna(v.z); v.w = tf32_rna(v.w);
    dst[(size_t)blockIdx.y * n4 + i] = v;
}

// ---------------------------------------------------------------------------
// mma.sync tf32 NT GEMM: C[M,1024] = A[M,1024] * B[1024,1024]^T + bias
// CTA 128x128, 8 warps (4m x 2n), warp 32x64. K-chunk 32, 2-stage cp.async.
// ---------------------------------------------------------------------------
#define GP        36
#define G_HALF    (128 * GP * 4)
#define G_STAGE   (2 * G_HALF)
#define G_SMEM    (2 * G_STAGE)             // 73728 B

__device__ __forceinline__ void g_load(uint32_t dstA, uint32_t dstB,
                                       const float* __restrict__ A,
                                       const float* __restrict__ B,
                                       int bm, int bn, int k0, int tid) {
#pragma unroll
    for (int i = 0; i < 4; ++i) {
        const int idx = tid + i * 256;
        const int row = idx >> 3, q = idx & 7;
        cp_async16(dstA + row * (GP * 4) + q * 16,
                   A + (size_t)(bm + row) * DMODEL + k0 + q * 4);
        cp_async16(dstB + row * (GP * 4) + q * 16,
                   B + (size_t)(bn + row) * DMODEL + k0 + q * 4);
    }
}

__global__ __launch_bounds__(256, 2)
void gemm_mma(const float* __restrict__ A, const float* __restrict__ B,
              const float* __restrict__ bias, float* __restrict__ C)
{
    extern __shared__ __align__(16) char smem[];
    const uint32_t sb = smem_u32(smem);
    const int tid  = threadIdx.x;
    const int lane = tid & 31, wid = tid >> 5;
    const int g = lane >> 2, t = lane & 3;
    const int wm = wid & 3, wn = wid >> 2;
    const int bm = blockIdx.y * 128, bn = blockIdx.x * 128;

    float acc[2][8][4];
#pragma unroll
    for (int ms = 0; ms < 2; ++ms)
#pragma unroll
        for (int ns = 0; ns < 8; ++ns)
#pragma unroll
            for (int k = 0; k < 4; ++k) acc[ms][ns][k] = 0.f;

    g_load(sb,           sb + G_HALF,           A, B, bm, bn, 0,  tid);
    cp_commit();
    g_load(sb + G_STAGE, sb + G_STAGE + G_HALF, A, B, bm, bn, 32, tid);
    cp_commit();

    const int NCH = DMODEL / 32;
    for (int c = 0; c < NCH; ++c) {
        if (c < NCH - 1) cp_wait<1>(); else cp_wait<0>();
        __syncthreads();

        const int s = c & 1;
        const float* As = (const float*)(smem + s * G_STAGE);
        const float* Bs = (const float*)(smem + s * G_STAGE + G_HALF);
#pragma unroll
        for (int ks = 0; ks < 4; ++ks) {
            float a[2][4];
#pragma unroll
            for (int ms = 0; ms < 2; ++ms) {
                const float* ap = As + (wm * 32 + ms * 16 + g) * GP + ks * 8 + t;
                a[ms][0] = ap[0];
                a[ms][1] = ap[8 * GP];
                a[ms][2] = ap[4];
                a[ms][3] = ap[8 * GP + 4];
            }
#pragma unroll
            for (int ns = 0; ns < 8; ++ns) {
                const float* bp = Bs + (wn * 64 + ns * 8 + g) * GP + ks * 8 + t;
                const float b0 = bp[0], b1 = bp[4];
                mma_tf32(acc[0][ns], a[0][0], a[0][1], a[0][2], a[0][3], b0, b1);
                mma_tf32(acc[1][ns], a[1][0], a[1][1], a[1][2], a[1][3], b0, b1);
            }
        }
        __syncthreads();
        if (c + 2 < NCH) {
            g_load(sb + s * G_STAGE, sb + s * G_STAGE + G_HALF,
                   A, B, bm, bn, (c + 2) * 32, tid);
            cp_commit();
        }
    }

#pragma unroll
    for (int ms = 0; ms < 2; ++ms) {
        const int r0 = bm + wm * 32 + ms * 16 + g;
#pragma unroll
        for (int ns = 0; ns < 8; ++ns) {
            const int col = bn + wn * 64 + ns * 8 + 2 * t;
            const float2 bv = *(const float2*)(bias + col);
            float2 lo, hi;
            lo.x = acc[ms][ns][0] + bv.x; lo.y = acc[ms][ns][1] + bv.y;
            hi.x = acc[ms][ns][2] + bv.x; hi.y = acc[ms][ns][3] + bv.y;
            *(float2*)(C + (size_t)r0 * DMODEL + col) = lo;
            *(float2*)(C + (size_t)(r0 + 8) * DMODEL + col) = hi;
        }
    }
}

// ---------------------------------------------------------------------------
// Flash attention v3: f16 m16n8k16 MMA, f32 accumulate.
// 128 threads / 4 warps; block = 128 q rows; warp = 32 q rows x 64 kv.
// Smem (f16x2 words, row stride 36 words == 4 mod 32 -> conflict-free frags):
//   Qw [128][36]  (q rows, d halves, scaled)
//   Kw [64][36]   (kv rows, d halves)
//   Vw [64][36]   (d rows, kv halves -- transposed, packed kv pairs)
// P stays in registers: S C-frag pairs pack directly into PV A-frags.
// ---------------------------------------------------------------------------
#define FW 36
#define FA_WORDS (128 * FW + 64 * FW + 64 * FW)
#define FA_SMEM_BYTES (FA_WORDS * 4 + 64 * 4)

__global__ __launch_bounds__(128, 2)
void flash_f16(const float* __restrict__ Q, const float* __restrict__ K,
               const float* __restrict__ V, const int* __restrict__ mask,
               float* __restrict__ O)
{
    extern __shared__ __align__(16) uint32_t fsm[];
    uint32_t* Qw = fsm;                 // [128][FW]
    uint32_t* Kw = Qw + 128 * FW;       // [64][FW]
    uint32_t* Vw = Kw + 64 * FW;        // [64][FW]
    int*      mk = (int*)(Vw + 64 * FW);

    const int tid  = threadIdx.x;
    const int lane = tid & 31, w = tid >> 5;
    const int g = lane >> 2, t = lane & 3;
    const int b = blockIdx.z, h = blockIdx.y, qt = blockIdx.x;

    const float qscale = 1.4426950408889634f * 0.125f;   // log2(e)/sqrt(64)
    const float NEG = -1.4426950408889634e9f;            // -1e9 * log2(e)

    const float* Qbase = Q + ((size_t)b * MSEQ + qt * 128) * DMODEL + h * DKH;
    const float* Kbase = K + (size_t)b * MSEQ * DMODEL + h * DKH;
    const float* Vbase = V + (size_t)b * MSEQ * DMODEL + h * DKH;
    const int*   mp    = mask + b * MSEQ;

    // ---- stage Q (once): rows 2-per-warp, coalesced; f16 with scale ----
#pragma unroll
    for (int i = 0; i < 16; ++i) {
        const int idx = tid + i * 128;
        const int row = idx >> 4, q = idx & 15;
        float4 v = *(const float4*)(Qbase + (size_t)row * DMODEL + q * 4);
        uint2 wv;
        wv.x = f16x2_pack(v.x * qscale, v.y * qscale);
        wv.y = f16x2_pack(v.z * qscale, v.w * qscale);
        *(uint2*)(Qw + row * FW + q * 2) = wv;
    }

    float m_[2][2], l_[2][2];
#pragma unroll
    for (int ms = 0; ms < 2; ++ms) {
        m_[ms][0] = -3.0e38f; m_[ms][1] = -3.0e38f;
        l_[ms][0] = 0.f;      l_[ms][1] = 0.f;
    }
    float o[2][8][4];
#pragma unroll
    for (int ms = 0; ms < 2; ++ms)
#pragma unroll
        for (int ns = 0; ns < 8; ++ns)
#pragma unroll
            for (int k = 0; k < 4; ++k) o[ms][ns][k] = 0.f;

    __syncthreads();

    for (int kt = 0; kt < MSEQ / 64; ++kt) {
        // ---- stage K (row-major f16) ----
#pragma unroll
        for (int i = 0; i < 8; ++i) {
            const int idx = tid + i * 128;
            const int row = idx >> 4, q = idx & 15;
            float4 v = *(const float4*)(Kbase + (size_t)(kt * 64 + row) * DMODEL + q * 4);
            uint2 wv;
            wv.x = f16x2_pack(v.x, v.y);
            wv.y = f16x2_pack(v.z, v.w);
            *(uint2*)(Kw + row * FW + q * 2) = wv;
        }
        // ---- stage V transposed: word (d, kv-pair r) = {V[2r][d], V[2r+1][d]} ----
        {
            const int r = tid & 31, dc = tid >> 5;
            const float* v0p = Vbase + (size_t)(kt * 64 + 2 * r) * DMODEL;
            const float* v1p = v0p + DMODEL;
#pragma unroll
            for (int j = 0; j < 4; ++j) {
                const int d4 = dc * 16 + j * 4;
                float4 v0 = *(const float4*)(v0p + d4);
                float4 v1 = *(const float4*)(v1p + d4);
                Vw[(d4 + 0) * FW + r] = f16x2_pack(v0.x, v1.x);
                Vw[(d4 + 1) * FW + r] = f16x2_pack(v0.y, v1.y);
                Vw[(d4 + 2) * FW + r] = f16x2_pack(v0.z, v1.z);
                Vw[(d4 + 3) * FW + r] = f16x2_pack(v0.w, v1.w);
            }
        }
        if (tid < 64) mk[tid] = mp[kt * 64 + tid];
        __syncthreads();

        // ---- S = Q K^T  (f16 k16) ----
        float s_[2][8][4];
#pragma unroll
        for (int ms = 0; ms < 2; ++ms)
#pragma unroll
            for (int ns = 0; ns < 8; ++ns)
#pragma unroll
                for (int k = 0; k < 4; ++k) s_[ms][ns][k] = 0.f;

#pragma unroll
        for (int u = 0; u < 4; ++u) {
            uint32_t a[2][4];
#pragma unroll
            for (int ms = 0; ms < 2; ++ms) {
                const uint32_t* ap = Qw + (w * 32 + ms * 16 + g) * FW + u * 8 + t;
                a[ms][0] = ap[0];
                a[ms][1] = ap[8 * FW];
                a[ms][2] = ap[4];
                a[ms][3] = ap[8 * FW + 4];
            }
#pragma unroll
            for (int ns = 0; ns < 8; ++ns) {
                const uint32_t* bp = Kw + (ns * 8 + g) * FW + u * 8 + t;
                const uint32_t b0 = bp[0], b1 = bp[4];
                mma_f16(s_[0][ns], a[0][0], a[0][1], a[0][2], a[0][3], b0, b1);
                mma_f16(s_[1][ns], a[1][0], a[1][1], a[1][2], a[1][3], b0, b1);
            }
        }

        // ---- mask + online softmax (registers + 4-lane shfl) ----
        int mask0[8], mask1[8];
#pragma unroll
        for (int ns = 0; ns < 8; ++ns) {
            mask0[ns] = mk[ns * 8 + 2 * t];
            mask1[ns] = mk[ns * 8 + 2 * t + 1];
        }
#pragma unroll
        for (int ms = 0; ms < 2; ++ms) {
#pragma unroll
            for (int ns = 0; ns < 8; ++ns) {
                if (!mask0[ns]) { s_[ms][ns][0] = NEG; s_[ms][ns][2] = NEG; }
                if (!mask1[ns]) { s_[ms][ns][1] = NEG; s_[ms][ns][3] = NEG; }
            }
            float mx0 = s_[ms][0][0], mx1 = s_[ms][0][2];
#pragma unroll
            for (int ns = 0; ns < 8; ++ns) {
                mx0 = fmaxf(mx0, fmaxf(s_[ms][ns][0], s_[ms][ns][1]));
                mx1 = fmaxf(mx1, fmaxf(s_[ms][ns][2], s_[ms][ns][3]));
            }
            mx0 = fmaxf(mx0, __shfl_xor_sync(0xffffffffu, mx0, 1));
            mx0 = fmaxf(mx0, __shfl_xor_sync(0xffffffffu, mx0, 2));
            mx1 = fmaxf(mx1, __shfl_xor_sync(0xffffffffu, mx1, 1));
            mx1 = fmaxf(mx1, __shfl_xor_sync(0xffffffffu, mx1, 2));

            const float mn0 = fmaxf(m_[ms][0], mx0);
            const float mn1 = fmaxf(m_[ms][1], mx1);
            const float al0 = fast_exp2(m_[ms][0] - mn0);
            const float al1 = fast_exp2(m_[ms][1] - mn1);
            m_[ms][0] = mn0; m_[ms][1] = mn1;

            float sum0 = 0.f, sum1 = 0.f;
#pragma unroll
            for (int ns = 0; ns < 8; ++ns) {
                float p0 = fast_exp2(s_[ms][ns][0] - mn0);
                float p1 = fast_exp2(s_[ms][ns][1] - mn0);
                float p2 = fast_exp2(s_[ms][ns][2] - mn1);
                float p3 = fast_exp2(s_[ms][ns][3] - mn1);
                sum0 += p0 + p1; sum1 += p2 + p3;
                s_[ms][ns][0] = p0; s_[ms][ns][1] = p1;
                s_[ms][ns][2] = p2; s_[ms][ns][3] = p3;
            }
            sum0 += __shfl_xor_sync(0xffffffffu, sum0, 1);
            sum0 += __shfl_xor_sync(0xffffffffu, sum0, 2);
            sum1 += __shfl_xor_sync(0xffffffffu, sum1, 1);
            sum1 += __shfl_xor_sync(0xffffffffu, sum1, 2);
            l_[ms][0] = l_[ms][0] * al0 + sum0;
            l_[ms][1] = l_[ms][1] * al1 + sum1;
#pragma unroll
            for (int ns = 0; ns < 8; ++ns) {
                o[ms][ns][0] *= al0; o[ms][ns][1] *= al0;
                o[ms][ns][2] *= al1; o[ms][ns][3] *= al1;
            }
        }

        // ---- O += P V : P C-frag pairs pack directly into k16 A-frags ----
#pragma unroll
        for (int u = 0; u < 4; ++u) {
            uint32_t a[2][4];
#pragma unroll
            for (int ms = 0; ms < 2; ++ms) {
                a[ms][0] = f16x2_pack(s_[ms][2 * u][0],     s_[ms][2 * u][1]);
                a[ms][1] = f16x2_pack(s_[ms][2 * u][2],     s_[ms][2 * u][3]);
                a[ms][2] = f16x2_pack(s_[ms][2 * u + 1][0], s_[ms][2 * u + 1][1]);
                a[ms][3] = f16x2_pack(s_[ms][2 * u + 1][2], s_[ms][2 * u + 1][3]);
            }
#pragma unroll
            for (int ns = 0; ns < 8; ++ns) {
                const uint32_t* vp = Vw + (ns * 8 + g) * FW + u * 8 + t;
                const uint32_t b0 = vp[0], b1 = vp[4];
                mma_f16(o[0][ns], a[0][0], a[0][1], a[0][2], a[0][3], b0, b1);
                mma_f16(o[1][ns], a[1][0], a[1][1], a[1][2], a[1][3], b0, b1);
            }
        }
        __syncthreads();
    }

    // ---- epilogue: normalize, rna (feeds tf32 O-projection), store ----
#pragma unroll
    for (int ms = 0; ms < 2; ++ms) {
        const int r = w * 32 + ms * 16 + g;
        const float inv0 = 1.f / l_[ms][0];
        const float inv1 = 1.f / l_[ms][1];
        float* o0p = O + ((size_t)b * MSEQ + qt * 128 + r) * DMODEL + h * DKH;
        float* o1p = o0p + 8 * DMODEL;
#pragma unroll
        for (int ns = 0; ns < 8; ++ns) {
            const int col = ns * 8 + 2 * t;
            float2 lo, hi2;
            lo.x  = tf32_rna(o[ms][ns][0] * inv0);
            lo.y  = tf32_rna(o[ms][ns][1] * inv0);
            hi2.x = tf32_rna(o[ms][ns][2] * inv1);
            hi2.y = tf32_rna(o[ms][ns][3] * inv1);
            *(float2*)(o0p + col) = lo;
            *(float2*)(o1p + col) = hi2;
        }
    }
}

// ---------------------------------------------------------------------------
extern "C" void kernel_launch(void* const* d_in, const int* in_sizes, int n_in,
                              void* d_out, int out_size)
{
    const float* query = (const float*)d_in[0];
    const float* key   = (const float*)d_in[1];
    const float* value = (const float*)d_in[2];
    const int*   mask  = (const int*)  d_in[3];
    const float* Wq = (const float*)d_in[4];
    const float* bq = (const float*)d_in[5];
    const float* Wk = (const float*)d_in[6];
    const float* bk = (const float*)d_in[7];
    const float* Wv = (const float*)d_in[8];
    const float* bv = (const float*)d_in[9];
    const float* Wo = (const float*)d_in[10];
    const float* bo = (const float*)d_in[11];
    float* out = (float*)d_out;

    float *pQ, *pK, *pV, *pO, *pXq, *pXk, *pXv, *pW;
    cudaGetSymbolAddress((void**)&pQ,  g_Q);
    cudaGetSymbolAddress((void**)&pK,  g_K);
    cudaGetSymbolAddress((void**)&pV,  g_V);
    cudaGetSymbolAddress((void**)&pO,  g_O);
    cudaGetSymbolAddress((void**)&pXq, g_Xq);
    cudaGetSymbolAddress((void**)&pXk, g_Xk);
    cudaGetSymbolAddress((void**)&pXv, g_Xv);
    cudaGetSymbolAddress((void**)&pW,  g_W);

    const int nin4 = MTOT * DMODEL / 4;
    const int nw4  = DMODEL * DMODEL / 4;
    round_inputs_k<<<dim3((nin4 + 255) / 256, 3), 256>>>(
        (const float4*)query, (const float4*)key, (const float4*)value,
        (float4*)pXq, (float4*)pXk, (float4*)pXv, nin4);
    round_weights_k<<<dim3((nw4 + 255) / 256, 4), 256>>>(
        (const float4*)Wq, (const float4*)Wk, (const float4*)Wv, (const float4*)Wo,
        (float4*)pW, nw4);

    cudaFuncSetAttribute(gemm_mma, cudaFuncAttributeMaxDynamicSharedMemorySize, G_SMEM);
    cudaFuncSetAttribute(flash_f16, cudaFuncAttributeMaxDynamicSharedMemorySize, FA_SMEM_BYTES);

    dim3 ggrid(DMODEL / 128, MTOT / 128);   // (8, 64)
    gemm_mma<<<ggrid, 256, G_SMEM>>>(pXq, pW + 0 * (size_t)DMODEL * DMODEL, bq, pQ);
    gemm_mma<<<ggrid, 256, G_SMEM>>>(pXk, pW + 1 * (size_t)DMODEL * DMODEL, bk, pK);
    gemm_mma<<<ggrid, 256, G_SMEM>>>(pXv, pW + 2 * (size_t)DMODEL * DMODEL, bv, pV);

    flash_f16<<<dim3(MSEQ / 128, NHEAD, BATCH), 128, FA_SMEM_BYTES>>>(pQ, pK, pV, mask, pO);

    gemm_mma<<<ggrid, 256, G_SMEM>>>(pO, pW + 3 * (size_t)DMODEL * DMODEL, bo, out);
}

// round 7
// speedup vs baseline: 5.6726x; 1.5037x over previous
#include <cuda_runtime.h>
#include <cstdint>

#define BATCH  4
#define MSEQ   2048
#define DMODEL 1024
#define NHEAD  16
#define DKH    64
#define MTOT   (BATCH*MSEQ)   // 8192

// ---------------- scratch (device globals; no allocs allowed) ----------------
__device__ uint16_t g_hXq[(size_t)MTOT * DMODEL];
__device__ uint16_t g_hXk[(size_t)MTOT * DMODEL];
__device__ uint16_t g_hXv[(size_t)MTOT * DMODEL];
__device__ uint16_t g_hW [(size_t)4 * DMODEL * DMODEL];
__device__ uint16_t g_hQ [(size_t)MTOT * DMODEL];
__device__ uint16_t g_hK [(size_t)MTOT * DMODEL];
__device__ uint16_t g_hV [(size_t)MTOT * DMODEL];
__device__ uint16_t g_hO [(size_t)MTOT * DMODEL];

// ---------------- helpers ----------------
__device__ __forceinline__ float fast_exp2(float x) {
    float y; asm("ex2.approx.f32 %0, %1;" : "=f"(y) : "f"(x)); return y;
}
__device__ __forceinline__ uint32_t f16x2_pack(float lo, float hi) {
    uint32_t r; asm("cvt.rn.f16x2.f32 %0, %1, %2;" : "=r"(r) : "f"(hi), "f"(lo));
    return r;
}
__device__ __forceinline__ uint32_t prmt(uint32_t a, uint32_t b, uint32_t sel) {
    uint32_t d; asm("prmt.b32 %0, %1, %2, %3;" : "=r"(d) : "r"(a), "r"(b), "r"(sel));
    return d;
}
__device__ __forceinline__ uint32_t smem_u32(const void* p) {
    uint32_t a;
    asm("{ .reg .u64 t; cvta.to.shared.u64 t, %1; cvt.u32.u64 %0, t; }" : "=r"(a) : "l"(p));
    return a;
}
__device__ __forceinline__ void cp_async16(uint32_t dst, const void* src) {
    asm volatile("cp.async.cg.shared.global [%0], [%1], 16;" :: "r"(dst), "l"(src));
}
__device__ __forceinline__ void cp_commit() {
    asm volatile("cp.async.commit_group;" ::: "memory");
}
template <int N> __device__ __forceinline__ void cp_wait() {
    asm volatile("cp.async.wait_group %0;" :: "n"(N) : "memory");
}

// m16n8k16 f16 MMA (row.col), f32 accumulate in place
__device__ __forceinline__ void mma_f16(float c[4],
                                        uint32_t a0, uint32_t a1, uint32_t a2, uint32_t a3,
                                        uint32_t b0, uint32_t b1) {
    asm volatile("mma.sync.aligned.m16n8k16.row.col.f32.f16.f16.f32 "
                 "{%0,%1,%2,%3},{%4,%5,%6,%7},{%8,%9},{%0,%1,%2,%3};"
                 : "+f"(c[0]), "+f"(c[1]), "+f"(c[2]), "+f"(c[3])
                 : "r"(a0), "r"(a1), "r"(a2), "r"(a3), "r"(b0), "r"(b1));
}

// ---------------------------------------------------------------------------
// f32 -> f16 conversion passes (batched over tensors via blockIdx.y)
// ---------------------------------------------------------------------------
__global__ void cvt_inputs_k(const float4* __restrict__ s0, const float4* __restrict__ s1,
                             const float4* __restrict__ s2,
                             uint2* __restrict__ d0, uint2* __restrict__ d1,
                             uint2* __restrict__ d2, int n4) {
    int i = blockIdx.x * blockDim.x + threadIdx.x;
    if (i >= n4) return;
    const float4* s = (blockIdx.y == 0) ? s0 : (blockIdx.y == 1) ? s1 : s2;
    uint2*        d = (blockIdx.y == 0) ? d0 : (blockIdx.y == 1) ? d1 : d2;
    float4 v = s[i];
    uint2 o;
    o.x = f16x2_pack(v.x, v.y);
    o.y = f16x2_pack(v.z, v.w);
    d[i] = o;
}
__global__ void cvt_weights_k(const float4* __restrict__ w0, const float4* __restrict__ w1,
                              const float4* __restrict__ w2, const float4* __restrict__ w3,
                              uint2* __restrict__ dst, int n4) {
    int i = blockIdx.x * blockDim.x + threadIdx.x;
    if (i >= n4) return;
    const float4* s = (blockIdx.y == 0) ? w0 : (blockIdx.y == 1) ? w1
                    : (blockIdx.y == 2) ? w2 : w3;
    float4 v = s[i];
    uint2 o;
    o.x = f16x2_pack(v.x, v.y);
    o.y = f16x2_pack(v.z, v.w);
    dst[(size_t)blockIdx.y * n4 + i] = o;
}

// ---------------------------------------------------------------------------
// f16 NT GEMM: C[M,1024] = A[M,1024] * B[1024,1024]^T + bias, optional *oscale
// CTA 128x128, 8 warps (4m x 2n), warp 32x64. K-chunk 64, 2-stage cp.async.
// Smem rows: 64 halves = 32 words, padded stride 36 words -> conflict-free frags.
// F16OUT: write f16x2 packed (for Q/K/V, feeding flash); else f32 (final out).
// ---------------------------------------------------------------------------
#define GW       36
#define GH_BYTES (128 * GW * 4)          // 18432 B per matrix per stage
#define G_STAGE  (2 * GH_BYTES)          // 36864 B
#define G_SMEM   (2 * G_STAGE)           // 73728 B

__device__ __forceinline__ void gh_load(uint32_t dstA, uint32_t dstB,
                                        const uint16_t* __restrict__ A,
                                        const uint16_t* __restrict__ B,
                                        int bm, int bn, int k0, int tid) {
#pragma unroll
    for (int i = 0; i < 4; ++i) {
        const int idx = tid + i * 256;
        const int row = idx >> 3, q = idx & 7;       // q: 16B unit (8 halves)
        cp_async16(dstA + row * (GW * 4) + q * 16,
                   A + (size_t)(bm + row) * DMODEL + k0 + q * 8);
        cp_async16(dstB + row * (GW * 4) + q * 16,
                   B + (size_t)(bn + row) * DMODEL + k0 + q * 8);
    }
}

template <bool F16OUT>
__global__ __launch_bounds__(256, 2)
void gemm_h(const uint16_t* __restrict__ A, const uint16_t* __restrict__ B,
            const float* __restrict__ bias, void* __restrict__ Cv, float oscale)
{
    extern __shared__ __align__(16) uint32_t gsm[];
    const uint32_t sb = smem_u32(gsm);
    const int tid  = threadIdx.x;
    const int lane = tid & 31, wid = tid >> 5;
    const int g = lane >> 2, t = lane & 3;
    const int wm = wid & 3, wn = wid >> 2;
    const int bm = blockIdx.y * 128, bn = blockIdx.x * 128;

    float acc[2][8][4];
#pragma unroll
    for (int ms = 0; ms < 2; ++ms)
#pragma unroll
        for (int ns = 0; ns < 8; ++ns)
#pragma unroll
            for (int k = 0; k < 4; ++k) acc[ms][ns][k] = 0.f;

    gh_load(sb,           sb + GH_BYTES,           A, B, bm, bn, 0,  tid);
    cp_commit();
    gh_load(sb + G_STAGE, sb + G_STAGE + GH_BYTES, A, B, bm, bn, 64, tid);
    cp_commit();

    const int NCH = DMODEL / 64;    // 16 chunks
    for (int c = 0; c < NCH; ++c) {
        if (c < NCH - 1) cp_wait<1>(); else cp_wait<0>();
        __syncthreads();

        const int s = c & 1;
        const uint32_t* As = gsm + s * (G_STAGE / 4);
        const uint32_t* Bs = As + (GH_BYTES / 4);
#pragma unroll
        for (int u = 0; u < 4; ++u) {
            uint32_t a[2][4];
#pragma unroll
            for (int ms = 0; ms < 2; ++ms) {
                const uint32_t* ap = As + (wm * 32 + ms * 16 + g) * GW + u * 8 + t;
                a[ms][0] = ap[0];
                a[ms][1] = ap[8 * GW];
                a[ms][2] = ap[4];
                a[ms][3] = ap[8 * GW + 4];
            }
#pragma unroll
            for (int ns = 0; ns < 8; ++ns) {
                const uint32_t* bp = Bs + (wn * 64 + ns * 8 + g) * GW + u * 8 + t;
                const uint32_t b0 = bp[0], b1 = bp[4];
                mma_f16(acc[0][ns], a[0][0], a[0][1], a[0][2], a[0][3], b0, b1);
                mma_f16(acc[1][ns], a[1][0], a[1][1], a[1][2], a[1][3], b0, b1);
            }
        }
        __syncthreads();
        if (c + 2 < NCH) {
            gh_load(sb + s * G_STAGE, sb + s * G_STAGE + GH_BYTES,
                    A, B, bm, bn, (c + 2) * 64, tid);
            cp_commit();
        }
    }

#pragma unroll
    for (int ms = 0; ms < 2; ++ms) {
        const int r0 = bm + wm * 32 + ms * 16 + g;
#pragma unroll
        for (int ns = 0; ns < 8; ++ns) {
            const int col = bn + wn * 64 + ns * 8 + 2 * t;
            const float2 bv = *(const float2*)(bias + col);
            if (F16OUT) {
                uint32_t* c0 = (uint32_t*)Cv + (size_t)r0 * (DMODEL / 2);
                uint32_t* c1 = (uint32_t*)Cv + (size_t)(r0 + 8) * (DMODEL / 2);
                c0[col >> 1] = f16x2_pack((acc[ms][ns][0] + bv.x) * oscale,
                                          (acc[ms][ns][1] + bv.y) * oscale);
                c1[col >> 1] = f16x2_pack((acc[ms][ns][2] + bv.x) * oscale,
                                          (acc[ms][ns][3] + bv.y) * oscale);
            } else {
                float* C = (float*)Cv;
                float2 lo, hi;
                lo.x = acc[ms][ns][0] + bv.x; lo.y = acc[ms][ns][1] + bv.y;
                hi.x = acc[ms][ns][2] + bv.x; hi.y = acc[ms][ns][3] + bv.y;
                *(float2*)(C + (size_t)r0 * DMODEL + col) = lo;
                *(float2*)(C + (size_t)(r0 + 8) * DMODEL + col) = hi;
            }
        }
    }
}

// ---------------------------------------------------------------------------
// Flash attention v4: all-f16 inputs, f16 output, 256 threads / 8 warps.
// Warp = 16 q rows x 64 kv. Q pre-scaled by log2(e)/sqrt(dk) at projection.
// Smem words (stride FW=36): Qw[128][36], Kw[64][36], Vw[64][36] (transposed).
// ---------------------------------------------------------------------------
#define FW 36
#define FA_SMEM_BYTES ((128 * FW + 64 * FW + 64 * FW) * 4 + 64 * 4)

__global__ __launch_bounds__(256, 2)
void flash_f16(const uint16_t* __restrict__ Q, const uint16_t* __restrict__ K,
               const uint16_t* __restrict__ V, const int* __restrict__ mask,
               uint16_t* __restrict__ O)
{
    extern __shared__ __align__(16) uint32_t fsm[];
    uint32_t* Qw = fsm;                 // [128][FW]
    uint32_t* Kw = Qw + 128 * FW;       // [64][FW]
    uint32_t* Vw = Kw + 64 * FW;        // [64][FW] d-major, kv pairs packed
    int*      mk = (int*)(Vw + 64 * FW);

    const int tid  = threadIdx.x;
    const int lane = tid & 31, w = tid >> 5;
    const int g = lane >> 2, t = lane & 3;
    const int b = blockIdx.z, h = blockIdx.y, qt = blockIdx.x;

    const float NEG = -1.4426950408889634e9f;   // -1e9 * log2(e)

    const uint16_t* Qbase = Q + ((size_t)b * MSEQ + qt * 128) * DMODEL + h * DKH;
    const uint16_t* Kbase = K + (size_t)b * MSEQ * DMODEL + h * DKH;
    const uint16_t* Vbase = V + (size_t)b * MSEQ * DMODEL + h * DKH;
    const int*      mp    = mask + b * MSEQ;

    // ---- stage Q (once): 128 rows x 8 x 16B chunks ----
#pragma unroll
    for (int i = 0; i < 4; ++i) {
        const int idx = tid + i * 256;
        const int row = idx >> 3, q = idx & 7;
        uint4 v = *(const uint4*)(Qbase + (size_t)row * DMODEL + q * 8);
        *(uint4*)(Qw + row * FW + q * 4) = v;
    }

    float m_[2] = {-3.0e38f, -3.0e38f};
    float l_[2] = {0.f, 0.f};
    float o[8][4];
#pragma unroll
    for (int ns = 0; ns < 8; ++ns)
#pragma unroll
        for (int k = 0; k < 4; ++k) o[ns][k] = 0.f;

    __syncthreads();

    for (int kt = 0; kt < MSEQ / 64; ++kt) {
        // ---- stage K: 64 rows x 8 x 16B ----
#pragma unroll
        for (int i = 0; i < 2; ++i) {
            const int idx = tid + i * 256;
            const int row = idx >> 3, q = idx & 7;
            uint4 v = *(const uint4*)(Kbase + (size_t)(kt * 64 + row) * DMODEL + q * 8);
            *(uint4*)(Kw + row * FW + q * 4) = v;
        }
        // ---- stage V transposed via prmt: word(d, r) = {V[2r][d], V[2r+1][d]} ----
        {
            const int rl = (w & 3) * 8 + (lane & 7);       // kv pair 0..31
            const uint32_t* v0p = (const uint32_t*)(Vbase + (size_t)(kt * 64 + 2 * rl) * DMODEL);
            const uint32_t* v1p = v0p + (DMODEL / 2);
#pragma unroll
            for (int j = 0; j < 4; ++j) {
                const int dw = (lane >> 3) + 4 * j + 16 * (w >> 2);  // d-pair 0..31
                const uint32_t v0 = v0p[dw], v1 = v1p[dw];
                Vw[(2 * dw + 0) * FW + rl] = prmt(v0, v1, 0x5410u);
                Vw[(2 * dw + 1) * FW + rl] = prmt(v0, v1, 0x7632u);
            }
        }
        if (tid < 64) mk[tid] = mp[kt * 64 + tid];
        __syncthreads();

        // ---- S = Q K^T ----
        float s_[8][4];
#pragma unroll
        for (int ns = 0; ns < 8; ++ns)
#pragma unroll
            for (int k = 0; k < 4; ++k) s_[ns][k] = 0.f;

#pragma unroll
        for (int u = 0; u < 4; ++u) {
            uint32_t a[4];
            const uint32_t* ap = Qw + (w * 16 + g) * FW + u * 8 + t;
            a[0] = ap[0];
            a[1] = ap[8 * FW];
            a[2] = ap[4];
            a[3] = ap[8 * FW + 4];
#pragma unroll
            for (int ns = 0; ns < 8; ++ns) {
                const uint32_t* bp = Kw + (ns * 8 + g) * FW + u * 8 + t;
                mma_f16(s_[ns], a[0], a[1], a[2], a[3], bp[0], bp[4]);
            }
        }

        // ---- mask + online softmax ----
#pragma unroll
        for (int ns = 0; ns < 8; ++ns) {
            if (!mk[ns * 8 + 2 * t])     { s_[ns][0] = NEG; s_[ns][2] = NEG; }
            if (!mk[ns * 8 + 2 * t + 1]) { s_[ns][1] = NEG; s_[ns][3] = NEG; }
        }
        float mx0 = s_[0][0], mx1 = s_[0][2];
#pragma unroll
        for (int ns = 0; ns < 8; ++ns) {
            mx0 = fmaxf(mx0, fmaxf(s_[ns][0], s_[ns][1]));
            mx1 = fmaxf(mx1, fmaxf(s_[ns][2], s_[ns][3]));
        }
        mx0 = fmaxf(mx0, __shfl_xor_sync(0xffffffffu, mx0, 1));
        mx0 = fmaxf(mx0, __shfl_xor_sync(0xffffffffu, mx0, 2));
        mx1 = fmaxf(mx1, __shfl_xor_sync(0xffffffffu, mx1, 1));
        mx1 = fmaxf(mx1, __shfl_xor_sync(0xffffffffu, mx1, 2));

        const float mn0 = fmaxf(m_[0], mx0);
        const float mn1 = fmaxf(m_[1], mx1);
        const float al0 = fast_exp2(m_[0] - mn0);
        const float al1 = fast_exp2(m_[1] - mn1);
        m_[0] = mn0; m_[1] = mn1;

        float sum0 = 0.f, sum1 = 0.f;
#pragma unroll
        for (int ns = 0; ns < 8; ++ns) {
            float p0 = fast_exp2(s_[ns][0] - mn0);
            float p1 = fast_exp2(s_[ns][1] - mn0);
            float p2 = fast_exp2(s_[ns][2] - mn1);
            float p3 = fast_exp2(s_[ns][3] - mn1);
            sum0 += p0 + p1; sum1 += p2 + p3;
            s_[ns][0] = p0; s_[ns][1] = p1;
            s_[ns][2] = p2; s_[ns][3] = p3;
        }
        sum0 += __shfl_xor_sync(0xffffffffu, sum0, 1);
        sum0 += __shfl_xor_sync(0xffffffffu, sum0, 2);
        sum1 += __shfl_xor_sync(0xffffffffu, sum1, 1);
        sum1 += __shfl_xor_sync(0xffffffffu, sum1, 2);
        l_[0] = l_[0] * al0 + sum0;
        l_[1] = l_[1] * al1 + sum1;
#pragma unroll
        for (int ns = 0; ns < 8; ++ns) {
            o[ns][0] *= al0; o[ns][1] *= al0;
            o[ns][2] *= al1; o[ns][3] *= al1;
        }

        // ---- O += P V : C-frag pairs pack directly into k16 A-frags ----
#pragma unroll
        for (int u = 0; u < 4; ++u) {
            uint32_t a[4];
            a[0] = f16x2_pack(s_[2 * u][0],     s_[2 * u][1]);
            a[1] = f16x2_pack(s_[2 * u][2],     s_[2 * u][3]);
            a[2] = f16x2_pack(s_[2 * u + 1][0], s_[2 * u + 1][1]);
            a[3] = f16x2_pack(s_[2 * u + 1][2], s_[2 * u + 1][3]);
#pragma unroll
            for (int ns = 0; ns < 8; ++ns) {
                const uint32_t* vp = Vw + (ns * 8 + g) * FW + u * 8 + t;
                mma_f16(o[ns], a[0], a[1], a[2], a[3], vp[0], vp[4]);
            }
        }
        __syncthreads();
    }

    // ---- epilogue: normalize, pack f16, store ----
    {
        const int r = w * 16 + g;
        const float inv0 = 1.f / l_[0];
        const float inv1 = 1.f / l_[1];
        uint32_t* o0p = (uint32_t*)(O + ((size_t)b * MSEQ + qt * 128 + r) * DMODEL + h * DKH);
        uint32_t* o1p = o0p + 8 * (DMODEL / 2);
#pragma unroll
        for (int ns = 0; ns < 8; ++ns) {
            o0p[ns * 4 + t] = f16x2_pack(o[ns][0] * inv0, o[ns][1] * inv0);
            o1p[ns * 4 + t] = f16x2_pack(o[ns][2] * inv1, o[ns][3] * inv1);
        }
    }
}

// ---------------------------------------------------------------------------
extern "C" void kernel_launch(void* const* d_in, const int* in_sizes, int n_in,
                              void* d_out, int out_size)
{
    const float* query = (const float*)d_in[0];
    const float* key   = (const float*)d_in[1];
    const float* value = (const float*)d_in[2];
    const int*   mask  = (const int*)  d_in[3];
    const float* Wq = (const float*)d_in[4];
    const float* bq = (const float*)d_in[5];
    const float* Wk = (const float*)d_in[6];
    const float* bk = (const float*)d_in[7];
    const float* Wv = (const float*)d_in[8];
    const float* bv = (const float*)d_in[9];
    const float* Wo = (const float*)d_in[10];
    const float* bo = (const float*)d_in[11];
    float* out = (float*)d_out;

    uint16_t *pXq, *pXk, *pXv, *pW, *pQ, *pK, *pV, *pO;
    cudaGetSymbolAddress((void**)&pXq, g_hXq);
    cudaGetSymbolAddress((void**)&pXk, g_hXk);
    cudaGetSymbolAddress((void**)&pXv, g_hXv);
    cudaGetSymbolAddress((void**)&pW,  g_hW);
    cudaGetSymbolAddress((void**)&pQ,  g_hQ);
    cudaGetSymbolAddress((void**)&pK,  g_hK);
    cudaGetSymbolAddress((void**)&pV,  g_hV);
    cudaGetSymbolAddress((void**)&pO,  g_hO);

    const int nin4 = MTOT * DMODEL / 4;
    const int nw4  = DMODEL * DMODEL / 4;
    cvt_inputs_k<<<dim3((nin4 + 255) / 256, 3), 256>>>(
        (const float4*)query, (const float4*)key, (const float4*)value,
        (uint2*)pXq, (uint2*)pXk, (uint2*)pXv, nin4);
    cvt_weights_k<<<dim3((nw4 + 255) / 256, 4), 256>>>(
        (const float4*)Wq, (const float4*)Wk, (const float4*)Wv, (const float4*)Wo,
        (uint2*)pW, nw4);

    cudaFuncSetAttribute(gemm_h<true>,  cudaFuncAttributeMaxDynamicSharedMemorySize, G_SMEM);
    cudaFuncSetAttribute(gemm_h<false>, cudaFuncAttributeMaxDynamicSharedMemorySize, G_SMEM);
    cudaFuncSetAttribute(flash_f16, cudaFuncAttributeMaxDynamicSharedMemorySize, FA_SMEM_BYTES);

    const float qscale = 1.4426950408889634f * 0.125f;   // log2(e)/sqrt(64)
    dim3 ggrid(DMODEL / 128, MTOT / 128);                // (8, 64)

    gemm_h<true><<<ggrid, 256, G_SMEM>>>(pXq, pW + 0 * (size_t)DMODEL * DMODEL, bq, pQ, qscale);
    gemm_h<true><<<ggrid, 256, G_SMEM>>>(pXk, pW + 1 * (size_t)DMODEL * DMODEL, bk, pK, 1.0f);
    gemm_h<true><<<ggrid, 256, G_SMEM>>>(pXv, pW + 2 * (size_t)DMODEL * DMODEL, bv, pV, 1.0f);

    flash_f16<<<dim3(MSEQ / 128, NHEAD, BATCH), 256, FA_SMEM_BYTES>>>(pQ, pK, pV, mask, pO);

    gemm_h<false><<<ggrid, 256, G_SMEM>>>(pO, pW + 3 * (size_t)DMODEL * DMODEL, bo, out, 1.0f);
}

// round 8
// speedup vs baseline: 7.0785x; 1.2478x over previous
#include <cuda_runtime.h>
#include <cstdint>

#define BATCH  4
#define MSEQ   2048
#define DMODEL 1024
#define NHEAD  16
#define DKH    64
#define MTOT   (BATCH*MSEQ)   // 8192

// ---------------- scratch (device globals; no allocs allowed) ----------------
__device__ uint16_t g_hXq[(size_t)MTOT * DMODEL];
__device__ uint16_t g_hXk[(size_t)MTOT * DMODEL];
__device__ uint16_t g_hXv[(size_t)MTOT * DMODEL];
__device__ uint16_t g_hW [(size_t)4 * DMODEL * DMODEL];
__device__ uint16_t g_hQ [(size_t)MTOT * DMODEL];
__device__ uint16_t g_hK [(size_t)MTOT * DMODEL];
__device__ uint16_t g_hV [(size_t)MTOT * DMODEL];
__device__ uint16_t g_hO [(size_t)MTOT * DMODEL];

// ---------------- helpers ----------------
__device__ __forceinline__ float fast_exp2(float x) {
    float y; asm("ex2.approx.f32 %0, %1;" : "=f"(y) : "f"(x)); return y;
}
__device__ __forceinline__ uint32_t f16x2_pack(float lo, float hi) {
    uint32_t r; asm("cvt.rn.f16x2.f32 %0, %1, %2;" : "=r"(r) : "f"(hi), "f"(lo));
    return r;
}
__device__ __forceinline__ uint32_t smem_u32(const void* p) {
    uint32_t a;
    asm("{ .reg .u64 t; cvta.to.shared.u64 t, %1; cvt.u32.u64 %0, t; }" : "=r"(a) : "l"(p));
    return a;
}
__device__ __forceinline__ void cp_async16(uint32_t dst, const void* src) {
    asm volatile("cp.async.cg.shared.global [%0], [%1], 16;" :: "r"(dst), "l"(src));
}
__device__ __forceinline__ void cp_commit() {
    asm volatile("cp.async.commit_group;" ::: "memory");
}
template <int N> __device__ __forceinline__ void cp_wait() {
    asm volatile("cp.async.wait_group %0;" :: "n"(N) : "memory");
}
__device__ __forceinline__ void ldsm_x4(uint32_t& r0, uint32_t& r1, uint32_t& r2,
                                        uint32_t& r3, uint32_t addr) {
    asm volatile("ldmatrix.sync.aligned.m8n8.x4.shared.b16 {%0,%1,%2,%3}, [%4];"
                 : "=r"(r0), "=r"(r1), "=r"(r2), "=r"(r3) : "r"(addr));
}
__device__ __forceinline__ void ldsm_x4_t(uint32_t& r0, uint32_t& r1, uint32_t& r2,
                                          uint32_t& r3, uint32_t addr) {
    asm volatile("ldmatrix.sync.aligned.m8n8.x4.trans.shared.b16 {%0,%1,%2,%3}, [%4];"
                 : "=r"(r0), "=r"(r1), "=r"(r2), "=r"(r3) : "r"(addr));
}

// m16n8k16 f16 MMA (row.col), f32 accumulate in place
__device__ __forceinline__ void mma_f16(float c[4],
                                        uint32_t a0, uint32_t a1, uint32_t a2, uint32_t a3,
                                        uint32_t b0, uint32_t b1) {
    asm volatile("mma.sync.aligned.m16n8k16.row.col.f32.f16.f16.f32 "
                 "{%0,%1,%2,%3},{%4,%5,%6,%7},{%8,%9},{%0,%1,%2,%3};"
                 : "+f"(c[0]), "+f"(c[1]), "+f"(c[2]), "+f"(c[3])
                 : "r"(a0), "r"(a1), "r"(a2), "r"(a3), "r"(b0), "r"(b1));
}

// ---------------------------------------------------------------------------
// f32 -> f16 conversion passes
// ---------------------------------------------------------------------------
__global__ void cvt_inputs_k(const float4* __restrict__ s0, const float4* __restrict__ s1,
                             const float4* __restrict__ s2,
                             uint2* __restrict__ d0, uint2* __restrict__ d1,
                             uint2* __restrict__ d2, int n4) {
    int i = blockIdx.x * blockDim.x + threadIdx.x;
    if (i >= n4) return;
    const float4* s = (blockIdx.y == 0) ? s0 : (blockIdx.y == 1) ? s1 : s2;
    uint2*        d = (blockIdx.y == 0) ? d0 : (blockIdx.y == 1) ? d1 : d2;
    float4 v = s[i];
    uint2 o;
    o.x = f16x2_pack(v.x, v.y);
    o.y = f16x2_pack(v.z, v.w);
    d[i] = o;
}
__global__ void cvt_weights_k(const float4* __restrict__ w0, const float4* __restrict__ w1,
                              const float4* __restrict__ w2, const float4* __restrict__ w3,
                              uint2* __restrict__ dst, int n4) {
    int i = blockIdx.x * blockDim.x + threadIdx.x;
    if (i >= n4) return;
    const float4* s = (blockIdx.y == 0) ? w0 : (blockIdx.y == 1) ? w1
                    : (blockIdx.y == 2) ? w2 : w3;
    float4 v = s[i];
    uint2 o;
    o.x = f16x2_pack(v.x, v.y);
    o.y = f16x2_pack(v.z, v.w);
    dst[(size_t)blockIdx.y * n4 + i] = o;
}

// ---------------------------------------------------------------------------
// f16 NT GEMM with ldmatrix: C = A * B^T + bias (opt *oscale, opt f16 out)
// CTA 128x128, 8 warps (4m x 2n), K-chunk 64, 2-stage cp.async.
// Smem rows 64 halves, padded stride GW=36 words (conflict-free ldmatrix).
// ---------------------------------------------------------------------------
#define GW       36
#define GH_BYTES (128 * GW * 4)
#define G_STAGE  (2 * GH_BYTES)
#define G_SMEM   (2 * G_STAGE)            // 73728 B

__device__ __forceinline__ void gh_load(uint32_t dstA, uint32_t dstB,
                                        const uint16_t* __restrict__ A,
                                        const uint16_t* __restrict__ B,
                                        int bm, int bn, int k0, int tid) {
#pragma unroll
    for (int i = 0; i < 4; ++i) {
        const int idx = tid + i * 256;
        const int row = idx >> 3, q = idx & 7;
        cp_async16(dstA + row * (GW * 4) + q * 16,
                   A + (size_t)(bm + row) * DMODEL + k0 + q * 8);
        cp_async16(dstB + row * (GW * 4) + q * 16,
                   B + (size_t)(bn + row) * DMODEL + k0 + q * 8);
    }
}

template <bool F16OUT>
__global__ __launch_bounds__(256, 2)
void gemm_h(const uint16_t* __restrict__ A, const uint16_t* __restrict__ B,
            const float* __restrict__ bias, void* __restrict__ Cv, float oscale)
{
    extern __shared__ __align__(16) uint32_t gsm[];
    const uint32_t sb = smem_u32(gsm);
    const int tid  = threadIdx.x;
    const int lane = tid & 31, wid = tid >> 5;
    const int g = lane >> 2, t = lane & 3;
    const int wm = wid & 3, wn = wid >> 2;
    const int bm = blockIdx.y * 128, bn = blockIdx.x * 128;

    // ldmatrix per-lane byte offsets (relative to stage base)
    uint32_t aoff[2], boff[4];
#pragma unroll
    for (int ms = 0; ms < 2; ++ms)
        aoff[ms] = ((wm * 32 + ms * 16 + (lane & 15)) * GW + ((lane & 16) ? 4 : 0)) * 4;
#pragma unroll
    for (int p = 0; p < 4; ++p)
        boff[p] = GH_BYTES +
                  ((wn * 64 + p * 16 + (lane & 7) + ((lane & 16) ? 8 : 0)) * GW +
                   ((lane & 8) ? 4 : 0)) * 4;

    float acc[2][8][4];
#pragma unroll
    for (int ms = 0; ms < 2; ++ms)
#pragma unroll
        for (int ns = 0; ns < 8; ++ns)
#pragma unroll
            for (int k = 0; k < 4; ++k) acc[ms][ns][k] = 0.f;

    gh_load(sb, sb + GH_BYTES, A, B, bm, bn, 0, tid);
    cp_commit();

    const int NCH = DMODEL / 64;    // 16
    for (int c = 0; c < NCH; ++c) {
        cp_wait<0>();
        __syncthreads();
        if (c + 1 < NCH) {
            const int sn = (c + 1) & 1;
            gh_load(sb + sn * G_STAGE, sb + sn * G_STAGE + GH_BYTES,
                    A, B, bm, bn, (c + 1) * 64, tid);
            cp_commit();
        }
        const uint32_t st = sb + (c & 1) * G_STAGE;
#pragma unroll
        for (int u = 0; u < 4; ++u) {
            uint32_t a[2][4];
            ldsm_x4(a[0][0], a[0][1], a[0][2], a[0][3], st + aoff[0] + u * 32);
            ldsm_x4(a[1][0], a[1][1], a[1][2], a[1][3], st + aoff[1] + u * 32);
#pragma unroll
            for (int p = 0; p < 4; ++p) {
                uint32_t b0, b1, b2, b3;
                ldsm_x4(b0, b1, b2, b3, st + boff[p] + u * 32);
                mma_f16(acc[0][2 * p],     a[0][0], a[0][1], a[0][2], a[0][3], b0, b1);
                mma_f16(acc[1][2 * p],     a[1][0], a[1][1], a[1][2], a[1][3], b0, b1);
                mma_f16(acc[0][2 * p + 1], a[0][0], a[0][1], a[0][2], a[0][3], b2, b3);
                mma_f16(acc[1][2 * p + 1], a[1][0], a[1][1], a[1][2], a[1][3], b2, b3);
            }
        }
    }

#pragma unroll
    for (int ms = 0; ms < 2; ++ms) {
        const int r0 = bm + wm * 32 + ms * 16 + g;
#pragma unroll
        for (int ns = 0; ns < 8; ++ns) {
            const int col = bn + wn * 64 + ns * 8 + 2 * t;
            const float2 bv = *(const float2*)(bias + col);
            if (F16OUT) {
                uint32_t* c0 = (uint32_t*)Cv + (size_t)r0 * (DMODEL / 2);
                uint32_t* c1 = (uint32_t*)Cv + (size_t)(r0 + 8) * (DMODEL / 2);
                c0[col >> 1] = f16x2_pack((acc[ms][ns][0] + bv.x) * oscale,
                                          (acc[ms][ns][1] + bv.y) * oscale);
                c1[col >> 1] = f16x2_pack((acc[ms][ns][2] + bv.x) * oscale,
                                          (acc[ms][ns][3] + bv.y) * oscale);
            } else {
                float* C = (float*)Cv;
                float2 lo, hi;
                lo.x = acc[ms][ns][0] + bv.x; lo.y = acc[ms][ns][1] + bv.y;
                hi.x = acc[ms][ns][2] + bv.x; hi.y = acc[ms][ns][3] + bv.y;
                *(float2*)(C + (size_t)r0 * DMODEL + col) = lo;
                *(float2*)(C + (size_t)(r0 + 8) * DMODEL + col) = hi;
            }
        }
    }
}

// ---------------------------------------------------------------------------
// Flash attention v5: ldmatrix frags + double-buffered cp.async K/V staging.
// 256 threads / 8 warps; warp = 16 q rows x 64 kv. V staged row-major,
// PV B-frags via ldmatrix.trans (no explicit transpose).
// Smem words: Qw[128*36] | buf0: K[64*36] V[64*36] | buf1: K V | mk[2][64]
// ---------------------------------------------------------------------------
#define FW 36
#define FA_KV_WORDS   (64 * FW)
#define FA_BUF_WORDS  (2 * FA_KV_WORDS)
#define FA_Q_WORDS    (128 * FW)
#define FA_MK_OFF     (FA_Q_WORDS + 2 * FA_BUF_WORDS)
#define FA_SMEM_BYTES ((FA_MK_OFF + 128) * 4)

__global__ __launch_bounds__(256, 2)
void flash_f16(const uint16_t* __restrict__ Q, const uint16_t* __restrict__ K,
               const uint16_t* __restrict__ V, const int* __restrict__ mask,
               uint16_t* __restrict__ O)
{
    extern __shared__ __align__(16) uint32_t fsm[];
    const uint32_t sb = smem_u32(fsm);

    const int tid  = threadIdx.x;
    const int lane = tid & 31, w = tid >> 5;
    const int g = lane >> 2, t = lane & 3;
    const int b = blockIdx.z, h = blockIdx.y, qt = blockIdx.x;

    const float NEG = -1.4426950408889634e9f;   // -1e9 * log2(e)

    const uint16_t* Qbase = Q + ((size_t)b * MSEQ + qt * 128) * DMODEL + h * DKH;
    const uint16_t* Kbase = K + (size_t)b * MSEQ * DMODEL + h * DKH;
    const uint16_t* Vbase = V + (size_t)b * MSEQ * DMODEL + h * DKH;
    const int*      mp    = mask + b * MSEQ;

    // ---- stage Q (once) ----
#pragma unroll
    for (int i = 0; i < 4; ++i) {
        const int idx = tid + i * 256;
        const int row = idx >> 3, q = idx & 7;
        uint4 v = *(const uint4*)(Qbase + (size_t)row * DMODEL + q * 8);
        *(uint4*)(fsm + row * FW + q * 4) = v;
    }

    // ldmatrix per-lane offsets (bytes)
    const uint32_t qoff = ((w * 16 + (lane & 15)) * FW + ((lane & 16) ? 4 : 0)) * 4;
    uint32_t koff[4], voff[4];
#pragma unroll
    for (int p = 0; p < 4; ++p) {
        koff[p] = ((p * 16 + (lane & 7) + ((lane & 16) ? 8 : 0)) * FW +
                   ((lane & 8) ? 4 : 0)) * 4;
        voff[p] = (((lane & 7) + ((lane & 8) ? 8 : 0)) * FW +
                   (2 * p + ((lane & 16) ? 1 : 0)) * 4) * 4;
    }

    // ---- KV tile loader (cp.async), tile kt into buffer s ----
    auto load_kv = [&](int kt, int s) {
        const uint32_t kb = sb + (FA_Q_WORDS + s * FA_BUF_WORDS) * 4;
        const uint32_t vb = kb + FA_KV_WORDS * 4;
#pragma unroll
        for (int i = 0; i < 2; ++i) {
            const int idx = tid + i * 256;
            const int row = idx >> 3, q = idx & 7;
            const uint32_t d = row * (FW * 4) + q * 16;
            cp_async16(kb + d, Kbase + (size_t)(kt * 64 + row) * DMODEL + q * 8);
            cp_async16(vb + d, Vbase + (size_t)(kt * 64 + row) * DMODEL + q * 8);
        }
        if (tid < 16)
            cp_async16(sb + (FA_MK_OFF + s * 64) * 4 + tid * 16, mp + kt * 64 + tid * 4);
    };

    float m_[2] = {-3.0e38f, -3.0e38f};
    float l_[2] = {0.f, 0.f};
    float o[8][4];
#pragma unroll
    for (int ns = 0; ns < 8; ++ns)
#pragma unroll
        for (int k = 0; k < 4; ++k) o[ns][k] = 0.f;

    load_kv(0, 0);
    cp_commit();

    const int NT = MSEQ / 64;   // 32
    for (int kt = 0; kt < NT; ++kt) {
        cp_wait<0>();
        __syncthreads();
        if (kt + 1 < NT) { load_kv(kt + 1, (kt + 1) & 1); cp_commit(); }

        const int s = kt & 1;
        const uint32_t kbuf = sb + (FA_Q_WORDS + s * FA_BUF_WORDS) * 4;
        const uint32_t vbuf = kbuf + FA_KV_WORDS * 4;
        const int* mk = (const int*)(fsm + FA_MK_OFF + s * 64);

        // ---- S = Q K^T ----
        float s_[8][4];
#pragma unroll
        for (int ns = 0; ns < 8; ++ns)
#pragma unroll
            for (int k = 0; k < 4; ++k) s_[ns][k] = 0.f;

#pragma unroll
        for (int u = 0; u < 4; ++u) {
            uint32_t a0, a1, a2, a3;
            ldsm_x4(a0, a1, a2, a3, sb + qoff + u * 32);
#pragma unroll
            for (int p = 0; p < 4; ++p) {
                uint32_t b0, b1, b2, b3;
                ldsm_x4(b0, b1, b2, b3, kbuf + koff[p] + u * 32);
                mma_f16(s_[2 * p],     a0, a1, a2, a3, b0, b1);
                mma_f16(s_[2 * p + 1], a0, a1, a2, a3, b2, b3);
            }
        }

        // ---- mask + online softmax ----
#pragma unroll
        for (int ns = 0; ns < 8; ++ns) {
            if (!mk[ns * 8 + 2 * t])     { s_[ns][0] = NEG; s_[ns][2] = NEG; }
            if (!mk[ns * 8 + 2 * t + 1]) { s_[ns][1] = NEG; s_[ns][3] = NEG; }
        }
        float mx0 = s_[0][0], mx1 = s_[0][2];
#pragma unroll
        for (int ns = 0; ns < 8; ++ns) {
            mx0 = fmaxf(mx0, fmaxf(s_[ns][0], s_[ns][1]));
            mx1 = fmaxf(mx1, fmaxf(s_[ns][2], s_[ns][3]));
        }
        mx0 = fmaxf(mx0, __shfl_xor_sync(0xffffffffu, mx0, 1));
        mx0 = fmaxf(mx0, __shfl_xor_sync(0xffffffffu, mx0, 2));
        mx1 = fmaxf(mx1, __shfl_xor_sync(0xffffffffu, mx1, 1));
        mx1 = fmaxf(mx1, __shfl_xor_sync(0xffffffffu, mx1, 2));

        const float mn0 = fmaxf(m_[0], mx0);
        const float mn1 = fmaxf(m_[1], mx1);
        const float al0 = fast_exp2(m_[0] - mn0);
        const float al1 = fast_exp2(m_[1] - mn1);
        m_[0] = mn0; m_[1] = mn1;

        float sum0 = 0.f, sum1 = 0.f;
#pragma unroll
        for (int ns = 0; ns < 8; ++ns) {
            float p0 = fast_exp2(s_[ns][0] - mn0);
            float p1 = fast_exp2(s_[ns][1] - mn0);
            float p2 = fast_exp2(s_[ns][2] - mn1);
            float p3 = fast_exp2(s_[ns][3] - mn1);
            sum0 += p0 + p1; sum1 += p2 + p3;
            s_[ns][0] = p0; s_[ns][1] = p1;
            s_[ns][2] = p2; s_[ns][3] = p3;
        }
        sum0 += __shfl_xor_sync(0xffffffffu, sum0, 1);
        sum0 += __shfl_xor_sync(0xffffffffu, sum0, 2);
        sum1 += __shfl_xor_sync(0xffffffffu, sum1, 1);
        sum1 += __shfl_xor_sync(0xffffffffu, sum1, 2);
        l_[0] = l_[0] * al0 + sum0;
        l_[1] = l_[1] * al1 + sum1;
#pragma unroll
        for (int ns = 0; ns < 8; ++ns) {
            o[ns][0] *= al0; o[ns][1] *= al0;
            o[ns][2] *= al1; o[ns][3] *= al1;
        }

        // ---- O += P V  (A packed from P, B via ldmatrix.trans on V rows) ----
#pragma unroll
        for (int u = 0; u < 4; ++u) {
            uint32_t a[4];
            a[0] = f16x2_pack(s_[2 * u][0],     s_[2 * u][1]);
            a[1] = f16x2_pack(s_[2 * u][2],     s_[2 * u][3]);
            a[2] = f16x2_pack(s_[2 * u + 1][0], s_[2 * u + 1][1]);
            a[3] = f16x2_pack(s_[2 * u + 1][2], s_[2 * u + 1][3]);
#pragma unroll
            for (int p = 0; p < 4; ++p) {
                uint32_t b0, b1, b2, b3;
                ldsm_x4_t(b0, b1, b2, b3, vbuf + voff[p] + u * (16 * FW * 4));
                mma_f16(o[2 * p],     a[0], a[1], a[2], a[3], b0, b1);
                mma_f16(o[2 * p + 1], a[0], a[1], a[2], a[3], b2, b3);
            }
        }
    }

    // ---- epilogue: normalize, pack f16, store ----
    {
        const int r = w * 16 + g;
        const float inv0 = 1.f / l_[0];
        const float inv1 = 1.f / l_[1];
        uint32_t* o0p = (uint32_t*)(O + ((size_t)b * MSEQ + qt * 128 + r) * DMODEL + h * DKH);
        uint32_t* o1p = o0p + 8 * (DMODEL / 2);
#pragma unroll
        for (int ns = 0; ns < 8; ++ns) {
            o0p[ns * 4 + t] = f16x2_pack(o[ns][0] * inv0, o[ns][1] * inv0);
            o1p[ns * 4 + t] = f16x2_pack(o[ns][2] * inv1, o[ns][3] * inv1);
        }
    }
}

// ---------------------------------------------------------------------------
extern "C" void kernel_launch(void* const* d_in, const int* in_sizes, int n_in,
                              void* d_out, int out_size)
{
    const float* query = (const float*)d_in[0];
    const float* key   = (const float*)d_in[1];
    const float* value = (const float*)d_in[2];
    const int*   mask  = (const int*)  d_in[3];
    const float* Wq = (const float*)d_in[4];
    const float* bq = (const float*)d_in[5];
    const float* Wk = (const float*)d_in[6];
    const float* bk = (const float*)d_in[7];
    const float* Wv = (const float*)d_in[8];
    const float* bv = (const float*)d_in[9];
    const float* Wo = (const float*)d_in[10];
    const float* bo = (const float*)d_in[11];
    float* out = (float*)d_out;

    uint16_t *pXq, *pXk, *pXv, *pW, *pQ, *pK, *pV, *pO;
    cudaGetSymbolAddress((void**)&pXq, g_hXq);
    cudaGetSymbolAddress((void**)&pXk, g_hXk);
    cudaGetSymbolAddress((void**)&pXv, g_hXv);
    cudaGetSymbolAddress((void**)&pW,  g_hW);
    cudaGetSymbolAddress((void**)&pQ,  g_hQ);
    cudaGetSymbolAddress((void**)&pK,  g_hK);
    cudaGetSymbolAddress((void**)&pV,  g_hV);
    cudaGetSymbolAddress((void**)&pO,  g_hO);

    const int nin4 = MTOT * DMODEL / 4;
    const int nw4  = DMODEL * DMODEL / 4;
    cvt_inputs_k<<<dim3((nin4 + 255) / 256, 3), 256>>>(
        (const float4*)query, (const float4*)key, (const float4*)value,
        (uint2*)pXq, (uint2*)pXk, (uint2*)pXv, nin4);
    cvt_weights_k<<<dim3((nw4 + 255) / 256, 4), 256>>>(
        (const float4*)Wq, (const float4*)Wk, (const float4*)Wv, (const float4*)Wo,
        (uint2*)pW, nw4);

    cudaFuncSetAttribute(gemm_h<true>,  cudaFuncAttributeMaxDynamicSharedMemorySize, G_SMEM);
    cudaFuncSetAttribute(gemm_h<false>, cudaFuncAttributeMaxDynamicSharedMemorySize, G_SMEM);
    cudaFuncSetAttribute(flash_f16, cudaFuncAttributeMaxDynamicSharedMemorySize, FA_SMEM_BYTES);

    const float qscale = 1.4426950408889634f * 0.125f;   // log2(e)/sqrt(64)
    dim3 ggrid(DMODEL / 128, MTOT / 128);                // (8, 64)

    gemm_h<true><<<ggrid, 256, G_SMEM>>>(pXq, pW + 0 * (size_t)DMODEL * DMODEL, bq, pQ, qscale);
    gemm_h<true><<<ggrid, 256, G_SMEM>>>(pXk, pW + 1 * (size_t)DMODEL * DMODEL, bk, pK, 1.0f);
    gemm_h<true><<<ggrid, 256, G_SMEM>>>(pXv, pW + 2 * (size_t)DMODEL * DMODEL, bv, pV, 1.0f);

    flash_f16<<<dim3(MSEQ / 128, NHEAD, BATCH), 256, FA_SMEM_BYTES>>>(pQ, pK, pV, mask, pO);

    gemm_h<false><<<ggrid, 256, G_SMEM>>>(pO, pW + 3 * (size_t)DMODEL * DMODEL, bo, out, 1.0f);
}

// round 11
// speedup vs baseline: 7.3111x; 1.0329x over previous
#include <cuda_runtime.h>
#include <cstdint>

#define BATCH  4
#define MSEQ   2048
#define DMODEL 1024
#define NHEAD  16
#define DKH    64
#define MTOT   (BATCH*MSEQ)   // 8192

// ---------------- scratch (device globals; no allocs allowed) ----------------
__device__ uint16_t g_hXq[(size_t)MTOT * DMODEL];
__device__ uint16_t g_hXk[(size_t)MTOT * DMODEL];
__device__ uint16_t g_hXv[(size_t)MTOT * DMODEL];
__device__ uint16_t g_hW [(size_t)4 * DMODEL * DMODEL];
__device__ uint16_t g_hQ [(size_t)MTOT * DMODEL];
__device__ uint16_t g_hK [(size_t)MTOT * DMODEL];
__device__ uint16_t g_hV [(size_t)MTOT * DMODEL];
__device__ uint16_t g_hO [(size_t)MTOT * DMODEL];

// ---------------- helpers ----------------
__device__ __forceinline__ float fast_exp2(float x) {
    float y; asm("ex2.approx.f32 %0, %1;" : "=f"(y) : "f"(x)); return y;
}
__device__ __forceinline__ uint32_t f16x2_pack(float lo, float hi) {
    uint32_t r; asm("cvt.rn.f16x2.f32 %0, %1, %2;" : "=r"(r) : "f"(hi), "f"(lo));
    return r;
}
__device__ __forceinline__ uint32_t smem_u32(const void* p) {
    uint32_t a;
    asm("{ .reg .u64 t; cvta.to.shared.u64 t, %1; cvt.u32.u64 %0, t; }" : "=r"(a) : "l"(p));
    return a;
}
__device__ __forceinline__ void cp_async16(uint32_t dst, const void* src) {
    asm volatile("cp.async.cg.shared.global [%0], [%1], 16;" :: "r"(dst), "l"(src));
}
__device__ __forceinline__ void cp_commit() {
    asm volatile("cp.async.commit_group;" ::: "memory");
}
template <int N> __device__ __forceinline__ void cp_wait() {
    asm volatile("cp.async.wait_group %0;" :: "n"(N) : "memory");
}
__device__ __forceinline__ void ldsm_x4(uint32_t& r0, uint32_t& r1, uint32_t& r2,
                                        uint32_t& r3, uint32_t addr) {
    asm volatile("ldmatrix.sync.aligned.m8n8.x4.shared.b16 {%0,%1,%2,%3}, [%4];"
                 : "=r"(r0), "=r"(r1), "=r"(r2), "=r"(r3) : "r"(addr));
}
__device__ __forceinline__ void ldsm_x4_t(uint32_t& r0, uint32_t& r1, uint32_t& r2,
                                          uint32_t& r3, uint32_t addr) {
    asm volatile("ldmatrix.sync.aligned.m8n8.x4.trans.shared.b16 {%0,%1,%2,%3}, [%4];"
                 : "=r"(r0), "=r"(r1), "=r"(r2), "=r"(r3) : "r"(addr));
}

// m16n8k16 f16 MMA (row.col), f32 accumulate in place
__device__ __forceinline__ void mma_f16(float c[4],
                                        uint32_t a0, uint32_t a1, uint32_t a2, uint32_t a3,
                                        uint32_t b0, uint32_t b1) {
    asm volatile("mma.sync.aligned.m16n8k16.row.col.f32.f16.f16.f32 "
                 "{%0,%1,%2,%3},{%4,%5,%6,%7},{%8,%9},{%0,%1,%2,%3};"
                 : "+f"(c[0]), "+f"(c[1]), "+f"(c[2]), "+f"(c[3])
                 : "r"(a0), "r"(a1), "r"(a2), "r"(a3), "r"(b0), "r"(b1));
}

// ---------------------------------------------------------------------------
// f32 -> f16 conversion passes
// ---------------------------------------------------------------------------
__global__ void cvt_inputs_k(const float4* __restrict__ s0, const float4* __restrict__ s1,
                             const float4* __restrict__ s2,
                             uint2* __restrict__ d0, uint2* __restrict__ d1,
                             uint2* __restrict__ d2, int n4) {
    int i = blockIdx.x * blockDim.x + threadIdx.x;
    if (i >= n4) return;
    const float4* s = (blockIdx.y == 0) ? s0 : (blockIdx.y == 1) ? s1 : s2;
    uint2*        d = (blockIdx.y == 0) ? d0 : (blockIdx.y == 1) ? d1 : d2;
    float4 v = s[i];
    uint2 o;
    o.x = f16x2_pack(v.x, v.y);
    o.y = f16x2_pack(v.z, v.w);
    d[i] = o;
}
__global__ void cvt_weights_k(const float4* __restrict__ w0, const float4* __restrict__ w1,
                              const float4* __restrict__ w2, const float4* __restrict__ w3,
                              uint2* __restrict__ dst, int n4) {
    int i = blockIdx.x * blockDim.x + threadIdx.x;
    if (i >= n4) return;
    const float4* s = (blockIdx.y == 0) ? w0 : (blockIdx.y == 1) ? w1
                    : (blockIdx.y == 2) ? w2 : w3;
    float4 v = s[i];
    uint2 o;
    o.x = f16x2_pack(v.x, v.y);
    o.y = f16x2_pack(v.z, v.w);
    dst[(size_t)blockIdx.y * n4 + i] = o;
}

// ---------------------------------------------------------------------------
// f16 NT GEMM body (ldmatrix + 3-stage cp.async), CTA 128x128, 8 warps.
// ---------------------------------------------------------------------------
#define GW       36
#define GH_BYTES (128 * GW * 4)
#define G_STAGE  (2 * GH_BYTES)           // 36864 B (A+B one stage)
#define G_SMEM   (3 * G_STAGE)            // 110592 B

__device__ __forceinline__ void gh_load(uint32_t dstA, uint32_t dstB,
                                        const uint16_t* __restrict__ A,
                                        const uint16_t* __restrict__ B,
                                        int bm, int bn, int k0, int tid) {
#pragma unroll
    for (int i = 0; i < 4; ++i) {
        const int idx = tid + i * 256;
        const int row = idx >> 3, q = idx & 7;
        cp_async16(dstA + row * (GW * 4) + q * 16,
                   A + (size_t)(bm + row) * DMODEL + k0 + q * 8);
        cp_async16(dstB + row * (GW * 4) + q * 16,
                   B + (size_t)(bn + row) * DMODEL + k0 + q * 8);
    }
}

template <bool F16OUT>
__device__ __forceinline__ void gemm_body(const uint16_t* __restrict__ A,
                                          const uint16_t* __restrict__ B,
                                          const float* __restrict__ bias,
                                          void* __restrict__ Cv, float oscale)
{
    extern __shared__ __align__(16) uint32_t gsm[];
    const uint32_t sb = smem_u32(gsm);
    const int tid  = threadIdx.x;
    const int lane = tid & 31, wid = tid >> 5;
    const int g = lane >> 2, t = lane & 3;
    const int wm = wid & 3, wn = wid >> 2;
    const int bm = blockIdx.y * 128, bn = blockIdx.x * 128;

    uint32_t aoff[2], boff[4];
#pragma unroll
    for (int ms = 0; ms < 2; ++ms)
        aoff[ms] = ((wm * 32 + ms * 16 + (lane & 15)) * GW + ((lane & 16) ? 4 : 0)) * 4;
#pragma unroll
    for (int p = 0; p < 4; ++p)
        boff[p] = GH_BYTES +
                  ((wn * 64 + p * 16 + (lane & 7) + ((lane & 16) ? 8 : 0)) * GW +
                   ((lane & 8) ? 4 : 0)) * 4;

    float acc[2][8][4];
#pragma unroll
    for (int ms = 0; ms < 2; ++ms)
#pragma unroll
        for (int ns = 0; ns < 8; ++ns)
#pragma unroll
            for (int k = 0; k < 4; ++k) acc[ms][ns][k] = 0.f;

    gh_load(sb + 0 * G_STAGE, sb + 0 * G_STAGE + GH_BYTES, A, B, bm, bn, 0,  tid);
    cp_commit();
    gh_load(sb + 1 * G_STAGE, sb + 1 * G_STAGE + GH_BYTES, A, B, bm, bn, 64, tid);
    cp_commit();

    const int NCH = DMODEL / 64;    // 16
    int st_c = 0, st_n = 2;         // stage of chunk c; stage for chunk c+2
    for (int c = 0; c < NCH; ++c) {
        if (c == NCH - 1) cp_wait<0>(); else cp_wait<1>();
        __syncthreads();
        if (c + 2 < NCH) {
            gh_load(sb + st_n * G_STAGE, sb + st_n * G_STAGE + GH_BYTES,
                    A, B, bm, bn, (c + 2) * 64, tid);
            cp_commit();
        }
        const uint32_t st = sb + st_c * G_STAGE;
        st_c = (st_c == 2) ? 0 : st_c + 1;
        st_n = (st_n == 2) ? 0 : st_n + 1;
#pragma unroll
        for (int u = 0; u < 4; ++u) {
            uint32_t a[2][4];
            ldsm_x4(a[0][0], a[0][1], a[0][2], a[0][3], st + aoff[0] + u * 32);
            ldsm_x4(a[1][0], a[1][1], a[1][2], a[1][3], st + aoff[1] + u * 32);
#pragma unroll
            for (int p = 0; p < 4; ++p) {
                uint32_t b0, b1, b2, b3;
                ldsm_x4(b0, b1, b2, b3, st + boff[p] + u * 32);
                mma_f16(acc[0][2 * p],     a[0][0], a[0][1], a[0][2], a[0][3], b0, b1);
                mma_f16(acc[1][2 * p],     a[1][0], a[1][1], a[1][2], a[1][3], b0, b1);
                mma_f16(acc[0][2 * p + 1], a[0][0], a[0][1], a[0][2], a[0][3], b2, b3);
                mma_f16(acc[1][2 * p + 1], a[1][0], a[1][1], a[1][2], a[1][3], b2, b3);
            }
        }
    }

#pragma unroll
    for (int ms = 0; ms < 2; ++ms) {
        const int r0 = bm + wm * 32 + ms * 16 + g;
#pragma unroll
        for (int ns = 0; ns < 8; ++ns) {
            const int col = bn + wn * 64 + ns * 8 + 2 * t;
            const float2 bv = *(const float2*)(bias + col);
            if (F16OUT) {
                uint32_t* c0 = (uint32_t*)Cv + (size_t)r0 * (DMODEL / 2);
                uint32_t* c1 = (uint32_t*)Cv + (size_t)(r0 + 8) * (DMODEL / 2);
                c0[col >> 1] = f16x2_pack((acc[ms][ns][0] + bv.x) * oscale,
                                          (acc[ms][ns][1] + bv.y) * oscale);
                c1[col >> 1] = f16x2_pack((acc[ms][ns][2] + bv.x) * oscale,
                                          (acc[ms][ns][3] + bv.y) * oscale);
            } else {
                float* C = (float*)Cv;
                float2 lo, hi;
                lo.x = acc[ms][ns][0] + bv.x; lo.y = acc[ms][ns][1] + bv.y;
                hi.x = acc[ms][ns][2] + bv.x; hi.y = acc[ms][ns][3] + bv.y;
                *(float2*)(C + (size_t)r0 * DMODEL + col) = lo;
                *(float2*)(C + (size_t)(r0 + 8) * DMODEL + col) = hi;
            }
        }
    }
}

// Merged Q/K/V projection: blockIdx.z selects input/weight/bias/output.
__global__ __launch_bounds__(256, 2)
void gemm_qkv(const uint16_t* __restrict__ Aq, const uint16_t* __restrict__ Ak,
              const uint16_t* __restrict__ Av, const uint16_t* __restrict__ W,
              const float* __restrict__ bq, const float* __restrict__ bk,
              const float* __restrict__ bv,
              uint16_t* __restrict__ Cq, uint16_t* __restrict__ Ck,
              uint16_t* __restrict__ Cvp, float qscale)
{
    const int z = blockIdx.z;
    const uint16_t* A = (z == 0) ? Aq : (z == 1) ? Ak : Av;
    const float*    b = (z == 0) ? bq : (z == 1) ? bk : bv;
    uint16_t*       C = (z == 0) ? Cq : (z == 1) ? Ck : Cvp;
    gemm_body<true>(A, W + (size_t)z * DMODEL * DMODEL, b, C,
                    (z == 0) ? qscale : 1.0f);
}

__global__ __launch_bounds__(256, 2)
void gemm_o(const uint16_t* __restrict__ A, const uint16_t* __restrict__ B,
            const float* __restrict__ bias, float* __restrict__ C)
{
    gemm_body<false>(A, B, bias, C, 1.0f);
}

// ---------------------------------------------------------------------------
// Flash attention v6: ldmatrix + Q-frags in registers + 3-stage KV cp.async.
// 256 threads / 8 warps; warp = 16 q rows x 64 kv.
// Smem words: Qw[128*36] | 3 x (K[64*36] V[64*36]) | mask 3x64
// ---------------------------------------------------------------------------
#define FW 36
#define FA_KV_WORDS   (64 * FW)
#define FA_BUF_WORDS  (2 * FA_KV_WORDS)
#define FA_Q_WORDS    (128 * FW)
#define FA_MK_OFF     (FA_Q_WORDS + 3 * FA_BUF_WORDS)
#define FA_SMEM_BYTES ((FA_MK_OFF + 3 * 64) * 4)

__global__ __launch_bounds__(256, 2)
void flash_f16(const uint16_t* __restrict__ Q, const uint16_t* __restrict__ K,
               const uint16_t* __restrict__ V, const int* __restrict__ mask,
               uint16_t* __restrict__ O)
{
    extern __shared__ __align__(16) uint32_t fsm[];
    const uint32_t sb = smem_u32(fsm);

    const int tid  = threadIdx.x;
    const int lane = tid & 31, w = tid >> 5;
    const int g = lane >> 2, t = lane & 3;
    const int b = blockIdx.z, h = blockIdx.y, qt = blockIdx.x;

    const float NEG = -1.4426950408889634e9f;   // -1e9 * log2(e)

    const uint16_t* Qbase = Q + ((size_t)b * MSEQ + qt * 128) * DMODEL + h * DKH;
    const uint16_t* Kbase = K + (size_t)b * MSEQ * DMODEL + h * DKH;
    const uint16_t* Vbase = V + (size_t)b * MSEQ * DMODEL + h * DKH;
    const int*      mp    = mask + b * MSEQ;

    // ---- stage Q ----
#pragma unroll
    for (int i = 0; i < 4; ++i) {
        const int idx = tid + i * 256;
        const int row = idx >> 3, q = idx & 7;
        uint4 v = *(const uint4*)(Qbase + (size_t)row * DMODEL + q * 8);
        *(uint4*)(fsm + row * FW + q * 4) = v;
    }

    // ldmatrix per-lane offsets (bytes)
    const uint32_t qoff = ((w * 16 + (lane & 15)) * FW + ((lane & 16) ? 4 : 0)) * 4;
    uint32_t koff[4], voff[4];
#pragma unroll
    for (int p = 0; p < 4; ++p) {
        koff[p] = ((p * 16 + (lane & 7) + ((lane & 16) ? 8 : 0)) * FW +
                   ((lane & 8) ? 4 : 0)) * 4;
        voff[p] = (((lane & 7) + ((lane & 8) ? 8 : 0)) * FW +
                   (2 * p + ((lane & 16) ? 1 : 0)) * 4) * 4;
    }

    auto load_kv = [&](int kt, int s) {
        const uint32_t kb = sb + (FA_Q_WORDS + s * FA_BUF_WORDS) * 4;
        const uint32_t vb = kb + FA_KV_WORDS * 4;
#pragma unroll
        for (int i = 0; i < 2; ++i) {
            const int idx = tid + i * 256;
            const int row = idx >> 3, q = idx & 7;
            const uint32_t d = row * (FW * 4) + q * 16;
            cp_async16(kb + d, Kbase + (size_t)(kt * 64 + row) * DMODEL + q * 8);
            cp_async16(vb + d, Vbase + (size_t)(kt * 64 + row) * DMODEL + q * 8);
        }
        if (tid < 16)
            cp_async16(sb + (FA_MK_OFF + s * 64) * 4 + tid * 16, mp + kt * 64 + tid * 4);
    };

    load_kv(0, 0);
    cp_commit();
    load_kv(1, 1);
    cp_commit();
    __syncthreads();   // Q stores visible

    // ---- hoist Q fragments (loop-invariant) ----
    uint32_t qf[4][4];
#pragma unroll
    for (int u = 0; u < 4; ++u)
        ldsm_x4(qf[u][0], qf[u][1], qf[u][2], qf[u][3], sb + qoff + u * 32);

    float m_[2] = {-3.0e38f, -3.0e38f};
    float l_[2] = {0.f, 0.f};
    float o[8][4];
#pragma unroll
    for (int ns = 0; ns < 8; ++ns)
#pragma unroll
        for (int k = 0; k < 4; ++k) o[ns][k] = 0.f;

    const int NT = MSEQ / 64;   // 32
    int st_c = 0, st_n = 2;
    for (int kt = 0; kt < NT; ++kt) {
        if (kt == NT - 1) cp_wait<0>(); else cp_wait<1>();
        __syncthreads();
        if (kt + 2 < NT) { load_kv(kt + 2, st_n); cp_commit(); }

        const uint32_t kbuf = sb + (FA_Q_WORDS + st_c * FA_BUF_WORDS) * 4;
        const uint32_t vbuf = kbuf + FA_KV_WORDS * 4;
        const int* mk = (const int*)(fsm + FA_MK_OFF + st_c * 64);
        st_c = (st_c == 2) ? 0 : st_c + 1;
        st_n = (st_n == 2) ? 0 : st_n + 1;

        // ---- S = Q K^T ----
        float s_[8][4];
#pragma unroll
        for (int ns = 0; ns < 8; ++ns)
#pragma unroll
            for (int k = 0; k < 4; ++k) s_[ns][k] = 0.f;

#pragma unroll
        for (int u = 0; u < 4; ++u) {
#pragma unroll
            for (int p = 0; p < 4; ++p) {
                uint32_t b0, b1, b2, b3;
                ldsm_x4(b0, b1, b2, b3, kbuf + koff[p] + u * 32);
                mma_f16(s_[2 * p],     qf[u][0], qf[u][1], qf[u][2], qf[u][3], b0, b1);
                mma_f16(s_[2 * p + 1], qf[u][0], qf[u][1], qf[u][2], qf[u][3], b2, b3);
            }
        }

        // ---- mask + online softmax ----
#pragma unroll
        for (int ns = 0; ns < 8; ++ns) {
            if (!mk[ns * 8 + 2 * t])     { s_[ns][0] = NEG; s_[ns][2] = NEG; }
            if (!mk[ns * 8 + 2 * t + 1]) { s_[ns][1] = NEG; s_[ns][3] = NEG; }
        }
        float mx0 = s_[0][0], mx1 = s_[0][2];
#pragma unroll
        for (int ns = 0; ns < 8; ++ns) {
            mx0 = fmaxf(mx0, fmaxf(s_[ns][0], s_[ns][1]));
            mx1 = fmaxf(mx1, fmaxf(s_[ns][2], s_[ns][3]));
        }
        mx0 = fmaxf(mx0, __shfl_xor_sync(0xffffffffu, mx0, 1));
        mx0 = fmaxf(mx0, __shfl_xor_sync(0xffffffffu, mx0, 2));
        mx1 = fmaxf(mx1, __shfl_xor_sync(0xffffffffu, mx1, 1));
        mx1 = fmaxf(mx1, __shfl_xor_sync(0xffffffffu, mx1, 2));

        const float mn0 = fmaxf(m_[0], mx0);
        const float mn1 = fmaxf(m_[1], mx1);
        const float al0 = fast_exp2(m_[0] - mn0);
        const float al1 = fast_exp2(m_[1] - mn1);
        m_[0] = mn0; m_[1] = mn1;

        float sum0 = 0.f, sum1 = 0.f;
#pragma unroll
        for (int ns = 0; ns < 8; ++ns) {
            float p0 = fast_exp2(s_[ns][0] - mn0);
            float p1 = fast_exp2(s_[ns][1] - mn0);
            float p2 = fast_exp2(s_[ns][2] - mn1);
            float p3 = fast_exp2(s_[ns][3] - mn1);
            sum0 += p0 + p1; sum1 += p2 + p3;
            s_[ns][0] = p0; s_[ns][1] = p1;
            s_[ns][2] = p2; s_[ns][3] = p3;
        }
        sum0 += __shfl_xor_sync(0xffffffffu, sum0, 1);
        sum0 += __shfl_xor_sync(0xffffffffu, sum0, 2);
        sum1 += __shfl_xor_sync(0xffffffffu, sum1, 1);
        sum1 += __shfl_xor_sync(0xffffffffu, sum1, 2);
        l_[0] = l_[0] * al0 + sum0;
        l_[1] = l_[1] * al1 + sum1;
#pragma unroll
        for (int ns = 0; ns < 8; ++ns) {
            o[ns][0] *= al0; o[ns][1] *= al0;
            o[ns][2] *= al1; o[ns][3] *= al1;
        }

        // ---- O += P V ----
#pragma unroll
        for (int u = 0; u < 4; ++u) {
            uint32_t a[4];
            a[0] = f16x2_pack(s_[2 * u][0],     s_[2 * u][1]);
            a[1] = f16x2_pack(s_[2 * u][2],     s_[2 * u][3]);
            a[2] = f16x2_pack(s_[2 * u + 1][0], s_[2 * u + 1][1]);
            a[3] = f16x2_pack(s_[2 * u + 1][2], s_[2 * u + 1][3]);
#pragma unroll
            for (int p = 0; p < 4; ++p) {
                uint32_t b0, b1, b2, b3;
                ldsm_x4_t(b0, b1, b2, b3, vbuf + voff[p] + u * (16 * FW * 4));
                mma_f16(o[2 * p],     a[0], a[1], a[2], a[3], b0, b1);
                mma_f16(o[2 * p + 1], a[0], a[1], a[2], a[3], b2, b3);
            }
        }
    }

    // ---- epilogue ----
    {
        const int r = w * 16 + g;
        const float inv0 = 1.f / l_[0];
        const float inv1 = 1.f / l_[1];
        uint32_t* o0p = (uint32_t*)(O + ((size_t)b * MSEQ + qt * 128 + r) * DMODEL + h * DKH);
        uint32_t* o1p = o0p + 8 * (DMODEL / 2);
#pragma unroll
        for (int ns = 0; ns < 8; ++ns) {
            o0p[ns * 4 + t] = f16x2_pack(o[ns][0] * inv0, o[ns][1] * inv0);
            o1p[ns * 4 + t] = f16x2_pack(o[ns][2] * inv1, o[ns][3] * inv1);
        }
    }
}

// ---------------------------------------------------------------------------
extern "C" void kernel_launch(void* const* d_in, const int* in_sizes, int n_in,
                              void* d_out, int out_size)
{
    const float* query = (const float*)d_in[0];
    const float* key   = (const float*)d_in[1];
    const float* value = (const float*)d_in[2];
    const int*   mask  = (const int*)  d_in[3];
    const float* Wq = (const float*)d_in[4];
    const float* bq = (const float*)d_in[5];
    const float* Wk = (const float*)d_in[6];
    const float* bk = (const float*)d_in[7];
    const float* Wv = (const float*)d_in[8];
    const float* bv = (const float*)d_in[9];
    const float* Wo = (const float*)d_in[10];
    const float* bo = (const float*)d_in[11];
    float* out = (float*)d_out;

    uint16_t *pXq, *pXk, *pXv, *pW, *pQ, *pK, *pV, *pO;
    cudaGetSymbolAddress((void**)&pXq, g_hXq);
    cudaGetSymbolAddress((void**)&pXk, g_hXk);
    cudaGetSymbolAddress((void**)&pXv, g_hXv);
    cudaGetSymbolAddress((void**)&pW,  g_hW);
    cudaGetSymbolAddress((void**)&pQ,  g_hQ);
    cudaGetSymbolAddress((void**)&pK,  g_hK);
    cudaGetSymbolAddress((void**)&pV,  g_hV);
    cudaGetSymbolAddress((void**)&pO,  g_hO);

    const int nin4 = MTOT * DMODEL / 4;
    const int nw4  = DMODEL * DMODEL / 4;
    cvt_inputs_k<<<dim3((nin4 + 255) / 256, 3), 256>>>(
        (const float4*)query, (const float4*)key, (const float4*)value,
        (uint2*)pXq, (uint2*)pXk, (uint2*)pXv, nin4);
    cvt_weights_k<<<dim3((nw4 + 255) / 256, 4), 256>>>(
        (const float4*)Wq, (const float4*)Wk, (const float4*)Wv, (const float4*)Wo,
        (uint2*)pW, nw4);

    cudaFuncSetAttribute(gemm_qkv, cudaFuncAttributeMaxDynamicSharedMemorySize, G_SMEM);
    cudaFuncSetAttribute(gemm_o,   cudaFuncAttributeMaxDynamicSharedMemorySize, G_SMEM);
    cudaFuncSetAttribute(flash_f16, cudaFuncAttributeMaxDynamicSharedMemorySize, FA_SMEM_BYTES);

    const float qscale = 1.4426950408889634f * 0.125f;   // log2(e)/sqrt(64)

    gemm_qkv<<<dim3(DMODEL / 128, MTOT / 128, 3), 256, G_SMEM>>>(
        pXq, pXk, pXv, pW, bq, bk, bv, pQ, pK, pV, qscale);

    flash_f16<<<dim3(MSEQ / 128, NHEAD, BATCH), 256, FA_SMEM_BYTES>>>(pQ, pK, pV, mask, pO);

    gemm_o<<<dim3(DMODEL / 128, MTOT / 128), 256, G_SMEM>>>(
        pO, pW + 3 * (size_t)DMODEL * DMODEL, bo, out);
}